// round 1
// baseline (speedup 1.0000x reference)
#include <cuda_runtime.h>

#define N_TOK 4096
#define DIM   512
#define HID   2048
#define NE    8
#define NPAIR (N_TOK * 2)

// Scratch (static device allocations — no runtime alloc allowed)
__device__ float g_H[(size_t)NPAIR * HID];   // fc1 outputs per pair   (64 MB)
__device__ float g_O[(size_t)NPAIR * DIM];   // fc2 outputs per pair   (16 MB)
__device__ float g_pw[NPAIR];                // routing weight per pair
__device__ int   g_list[NE * NPAIR];         // pair ids grouped by expert
__device__ int   g_cnt[NE];                  // pairs per expert

// ---------------------------------------------------------------------------
// Zero counters + usage output (must run every launch: graph replays)
// ---------------------------------------------------------------------------
__global__ void k_zero(float* __restrict__ usage) {
    int t = threadIdx.x;
    if (t < NE) { g_cnt[t] = 0; usage[t] = 0.0f; }
}

// ---------------------------------------------------------------------------
// Gating: one warp per token. logits = x@Wg + bg; top-2; pairwise softmax.
// ---------------------------------------------------------------------------
__global__ void k_gate(const float* __restrict__ x,
                       const float* __restrict__ Wg,
                       const float* __restrict__ bg,
                       float* __restrict__ usage) {
    int n    = blockIdx.x * (blockDim.x >> 5) + (threadIdx.x >> 5);
    int lane = threadIdx.x & 31;
    if (n >= N_TOK) return;

    float p[NE];
#pragma unroll
    for (int e = 0; e < NE; e++) p[e] = 0.0f;

    const float* xr = x + (size_t)n * DIM;
    for (int d = lane; d < DIM; d += 32) {
        float xv = xr[d];
        const float* wr = Wg + (size_t)d * NE;
#pragma unroll
        for (int e = 0; e < NE; e++) p[e] = fmaf(xv, wr[e], p[e]);
    }
#pragma unroll
    for (int o = 16; o; o >>= 1)
#pragma unroll
        for (int e = 0; e < NE; e++) p[e] += __shfl_xor_sync(0xffffffffu, p[e], o);

    if (lane == 0) {
#pragma unroll
        for (int e = 0; e < NE; e++) p[e] += bg[e];
        // top-2, earliest index wins ties (matches lax.top_k)
        int i0 = 0;
#pragma unroll
        for (int e = 1; e < NE; e++) if (p[e] > p[i0]) i0 = e;
        int i1 = (i0 == 0) ? 1 : 0;
#pragma unroll
        for (int e = 0; e < NE; e++) if (e != i0 && p[e] > p[i1]) i1 = e;

        // renormalized top-2 softmax == pairwise sigmoid (denominator cancels)
        float w0 = 1.0f / (1.0f + expf(p[i1] - p[i0]));
        float w1 = 1.0f - w0;
        g_pw[2 * n + 0] = w0;
        g_pw[2 * n + 1] = w1;
        atomicAdd(&usage[i0], w0);
        atomicAdd(&usage[i1], w1);
        int q0 = atomicAdd(&g_cnt[i0], 1); g_list[i0 * NPAIR + q0] = 2 * n;
        int q1 = atomicAdd(&g_cnt[i1], 1); g_list[i1 * NPAIR + q1] = 2 * n + 1;
    }
}

// ---------------------------------------------------------------------------
// fc1: per-expert grouped GEMM.  H[pair] = x[token] @ W1[e] + b1[e]
// 64x64 tile, BK=16, 256 threads, 4x4 microtile, 1-deep register prefetch.
// ---------------------------------------------------------------------------
__global__ void k_fc1(const float* __restrict__ x,
                      const float* __restrict__ W1,
                      const float* __restrict__ b1) {
    const int e   = blockIdx.z;
    const int cnt = g_cnt[e];
    const int m0  = blockIdx.y * 64;
    if (m0 >= cnt) return;
    const int h0 = blockIdx.x * 64;

    __shared__ float As[64][16];
    __shared__ float Bs[16][64];

    const int tid = threadIdx.x;
    const int tx = tid & 15, ty = tid >> 4;

    // A loader: 64 rows x 16 cols, float4 per thread
    const int ar = tid >> 2;
    const int ac = (tid & 3) << 2;
    const float* arow = nullptr;
    {
        int m = m0 + ar;
        if (m < cnt) {
            int pid = g_list[e * NPAIR + m];
            arow = x + (size_t)(pid >> 1) * DIM;
        }
    }
    // B loader: 16 rows x 64 cols
    const int br = tid >> 4;
    const int bc = (tid & 15) << 2;
    const float* Bp = W1 + (size_t)e * DIM * HID + (size_t)br * HID + h0 + bc;

    float acc[4][4];
#pragma unroll
    for (int i = 0; i < 4; i++)
#pragma unroll
        for (int j = 0; j < 4; j++) acc[i][j] = 0.0f;

    float4 av = arow ? *(const float4*)(arow + ac) : make_float4(0, 0, 0, 0);
    float4 bv = *(const float4*)(Bp);

    for (int k0 = 0; k0 < DIM; k0 += 16) {
        __syncthreads();
        *(float4*)&As[ar][ac] = av;
        *(float4*)&Bs[br][bc] = bv;
        __syncthreads();
        int kn = k0 + 16;
        if (kn < DIM) {
            av = arow ? *(const float4*)(arow + kn + ac) : make_float4(0, 0, 0, 0);
            bv = *(const float4*)(Bp + (size_t)kn * HID);
        }
#pragma unroll
        for (int kk = 0; kk < 16; kk++) {
            float bb0 = Bs[kk][tx * 4 + 0];
            float bb1 = Bs[kk][tx * 4 + 1];
            float bb2 = Bs[kk][tx * 4 + 2];
            float bb3 = Bs[kk][tx * 4 + 3];
#pragma unroll
            for (int i = 0; i < 4; i++) {
                float a = As[ty * 4 + i][kk];
                acc[i][0] = fmaf(a, bb0, acc[i][0]);
                acc[i][1] = fmaf(a, bb1, acc[i][1]);
                acc[i][2] = fmaf(a, bb2, acc[i][2]);
                acc[i][3] = fmaf(a, bb3, acc[i][3]);
            }
        }
    }

    const float* b1e = b1 + (size_t)e * HID + h0 + tx * 4;
#pragma unroll
    for (int i = 0; i < 4; i++) {
        int m = m0 + ty * 4 + i;
        if (m < cnt) {
            int pid = g_list[e * NPAIR + m];
            float4 r;
            r.x = acc[i][0] + b1e[0];
            r.y = acc[i][1] + b1e[1];
            r.z = acc[i][2] + b1e[2];
            r.w = acc[i][3] + b1e[3];
            *(float4*)(g_H + (size_t)pid * HID + h0 + tx * 4) = r;
        }
    }
}

// ---------------------------------------------------------------------------
// fc2: per-expert grouped GEMM.  O[pair] = H[pair] @ W2[e] + b2[e]
// ---------------------------------------------------------------------------
__global__ void k_fc2(const float* __restrict__ W2,
                      const float* __restrict__ b2) {
    const int e   = blockIdx.z;
    const int cnt = g_cnt[e];
    const int m0  = blockIdx.y * 64;
    if (m0 >= cnt) return;
    const int n0 = blockIdx.x * 64;

    __shared__ float As[64][16];
    __shared__ float Bs[16][64];

    const int tid = threadIdx.x;
    const int tx = tid & 15, ty = tid >> 4;

    const int ar = tid >> 2;
    const int ac = (tid & 3) << 2;
    const float* arow = nullptr;
    {
        int m = m0 + ar;
        if (m < cnt) {
            int pid = g_list[e * NPAIR + m];
            arow = g_H + (size_t)pid * HID;
        }
    }
    const int br = tid >> 4;
    const int bc = (tid & 15) << 2;
    const float* Bp = W2 + (size_t)e * HID * DIM + (size_t)br * DIM + n0 + bc;

    float acc[4][4];
#pragma unroll
    for (int i = 0; i < 4; i++)
#pragma unroll
        for (int j = 0; j < 4; j++) acc[i][j] = 0.0f;

    float4 av = arow ? *(const float4*)(arow + ac) : make_float4(0, 0, 0, 0);
    float4 bv = *(const float4*)(Bp);

    for (int k0 = 0; k0 < HID; k0 += 16) {
        __syncthreads();
        *(float4*)&As[ar][ac] = av;
        *(float4*)&Bs[br][bc] = bv;
        __syncthreads();
        int kn = k0 + 16;
        if (kn < HID) {
            av = arow ? *(const float4*)(arow + kn + ac) : make_float4(0, 0, 0, 0);
            bv = *(const float4*)(Bp + (size_t)kn * DIM);
        }
#pragma unroll
        for (int kk = 0; kk < 16; kk++) {
            float bb0 = Bs[kk][tx * 4 + 0];
            float bb1 = Bs[kk][tx * 4 + 1];
            float bb2 = Bs[kk][tx * 4 + 2];
            float bb3 = Bs[kk][tx * 4 + 3];
#pragma unroll
            for (int i = 0; i < 4; i++) {
                float a = As[ty * 4 + i][kk];
                acc[i][0] = fmaf(a, bb0, acc[i][0]);
                acc[i][1] = fmaf(a, bb1, acc[i][1]);
                acc[i][2] = fmaf(a, bb2, acc[i][2]);
                acc[i][3] = fmaf(a, bb3, acc[i][3]);
            }
        }
    }

    const float* b2e = b2 + (size_t)e * DIM + n0 + tx * 4;
#pragma unroll
    for (int i = 0; i < 4; i++) {
        int m = m0 + ty * 4 + i;
        if (m < cnt) {
            int pid = g_list[e * NPAIR + m];
            float4 r;
            r.x = acc[i][0] + b2e[0];
            r.y = acc[i][1] + b2e[1];
            r.z = acc[i][2] + b2e[2];
            r.w = acc[i][3] + b2e[3];
            *(float4*)(g_O + (size_t)pid * DIM + n0 + tx * 4) = r;
        }
    }
}

// ---------------------------------------------------------------------------
// Combine: out[n] = w0 * O[2n] + w1 * O[2n+1]
// ---------------------------------------------------------------------------
__global__ void k_comb(float* __restrict__ out) {
    int idx = blockIdx.x * blockDim.x + threadIdx.x;   // over N*DIM/4
    if (idx >= N_TOK * DIM / 4) return;
    int n  = idx / (DIM / 4);
    int d4 = idx % (DIM / 4);
    float w0 = g_pw[2 * n + 0];
    float w1 = g_pw[2 * n + 1];
    float4 a = *(const float4*)(g_O + (size_t)(2 * n + 0) * DIM + d4 * 4);
    float4 b = *(const float4*)(g_O + (size_t)(2 * n + 1) * DIM + d4 * 4);
    float4 r;
    r.x = w0 * a.x + w1 * b.x;
    r.y = w0 * a.y + w1 * b.y;
    r.z = w0 * a.z + w1 * b.z;
    r.w = w0 * a.w + w1 * b.w;
    *(float4*)(out + (size_t)idx * 4) = r;
}

// ---------------------------------------------------------------------------
extern "C" void kernel_launch(void* const* d_in, const int* in_sizes, int n_in,
                              void* d_out, int out_size) {
    const float* x  = (const float*)d_in[0];
    const float* Wg = (const float*)d_in[1];
    const float* bg = (const float*)d_in[2];
    const float* W1 = (const float*)d_in[3];
    const float* b1 = (const float*)d_in[4];
    const float* W2 = (const float*)d_in[5];
    const float* b2 = (const float*)d_in[6];
    float* out   = (float*)d_out;
    float* usage = out + (size_t)N_TOK * DIM;

    k_zero<<<1, 32>>>(usage);
    k_gate<<<N_TOK / 4, 128>>>(x, Wg, bg, usage);
    k_fc1<<<dim3(HID / 64, NPAIR / 64, NE), 256>>>(x, W1, b1);
    k_fc2<<<dim3(DIM / 64, NPAIR / 64, NE), 256>>>(W2, b2);
    k_comb<<<(N_TOK * DIM / 4) / 256, 256>>>(out);
}

// round 6
// speedup vs baseline: 1.6890x; 1.6890x over previous
#include <cuda_runtime.h>
#include <cuda_bf16.h>
#include <mma.h>
#include <cstdint>

using namespace nvcuda;

#define N_TOK 4096
#define DIM   512
#define HID   2048
#define NE    8
#define NPAIR (N_TOK * 2)

// GEMM tiling: CTA 128x128, BK=32, 256 threads (8 warps), warp tile 32x64
#define M_T 128
#define N_T 128
#define BK  32

// smem pitches (elements): A rows 40 (80B), B rows 136 (272B); both mult of 8
#define ALD 40
#define BLD 136
static constexpr int SA_H = 0;              // 128*40*2 = 10240
static constexpr int SA_L = 10240;
static constexpr int SB_H = 20480;          // 32*136*2 = 8704
static constexpr int SB_L = 29184;
static constexpr int SM_BYTES = 37888;      // < 48KB static

// ---------------- scratch (static device memory; device-code access ONLY) ---
// NOTE: never pass these as kernel arguments from host — host code sees the
// host *shadow* symbol, not the device address (silent corruption via ATS).
__device__ __align__(256) __nv_bfloat16 g_xhi[(size_t)N_TOK * DIM];
__device__ __align__(256) __nv_bfloat16 g_xlo[(size_t)N_TOK * DIM];
__device__ __align__(256) __nv_bfloat16 g_w1hi[(size_t)NE * DIM * HID];
__device__ __align__(256) __nv_bfloat16 g_w1lo[(size_t)NE * DIM * HID];
__device__ __align__(256) __nv_bfloat16 g_w2hi[(size_t)NE * HID * DIM];
__device__ __align__(256) __nv_bfloat16 g_w2lo[(size_t)NE * HID * DIM];
__device__ __align__(256) __nv_bfloat16 g_Hhi[(size_t)NPAIR * HID];
__device__ __align__(256) __nv_bfloat16 g_Hlo[(size_t)NPAIR * HID];
__device__ __align__(256) float g_O[(size_t)NPAIR * DIM];
__device__ __align__(256) float g_pw[NPAIR];
__device__ __align__(256) int   g_list[NE * NPAIR];
__device__ int g_cnt[NE];

// ---------------- aux kernels ------------------------------------------------
__global__ void k_zero(float* __restrict__ usage) {
    int t = threadIdx.x;
    if (t < NE) { g_cnt[t] = 0; usage[t] = 0.0f; }
}

// fp32 -> bf16 hi/lo split body; wrappers pass globals from DEVICE code.
__device__ __forceinline__ void split_body(const float* __restrict__ src,
                                           __nv_bfloat16* hi,
                                           __nv_bfloat16* lo, int n4) {
    int i = blockIdx.x * blockDim.x + threadIdx.x;
    if (i >= n4) return;
    float4 v = ((const float4*)src)[i];
    __nv_bfloat16 h0 = __float2bfloat16(v.x), h1 = __float2bfloat16(v.y);
    __nv_bfloat16 h2 = __float2bfloat16(v.z), h3 = __float2bfloat16(v.w);
    ((__nv_bfloat162*)hi)[i * 2 + 0] = __halves2bfloat162(h0, h1);
    ((__nv_bfloat162*)hi)[i * 2 + 1] = __halves2bfloat162(h2, h3);
    ((__nv_bfloat162*)lo)[i * 2 + 0] = __halves2bfloat162(
        __float2bfloat16(v.x - __bfloat162float(h0)),
        __float2bfloat16(v.y - __bfloat162float(h1)));
    ((__nv_bfloat162*)lo)[i * 2 + 1] = __halves2bfloat162(
        __float2bfloat16(v.z - __bfloat162float(h2)),
        __float2bfloat16(v.w - __bfloat162float(h3)));
}

__global__ void k_split_x(const float* __restrict__ src) {
    split_body(src, g_xhi, g_xlo, N_TOK * DIM / 4);
}
__global__ void k_split_w1(const float* __restrict__ src) {
    split_body(src, g_w1hi, g_w1lo, NE * DIM * HID / 4);
}
__global__ void k_split_w2(const float* __restrict__ src) {
    split_body(src, g_w2hi, g_w2lo, NE * HID * DIM / 4);
}

__global__ void k_gate(const float* __restrict__ x,
                       const float* __restrict__ Wg,
                       const float* __restrict__ bg,
                       float* __restrict__ usage) {
    int n    = blockIdx.x * (blockDim.x >> 5) + (threadIdx.x >> 5);
    int lane = threadIdx.x & 31;
    if (n >= N_TOK) return;
    float p[NE];
#pragma unroll
    for (int e = 0; e < NE; e++) p[e] = 0.0f;
    const float* xr = x + (size_t)n * DIM;
    for (int d = lane; d < DIM; d += 32) {
        float xv = xr[d];
        const float* wr = Wg + (size_t)d * NE;
#pragma unroll
        for (int e = 0; e < NE; e++) p[e] = fmaf(xv, wr[e], p[e]);
    }
#pragma unroll
    for (int o = 16; o; o >>= 1)
#pragma unroll
        for (int e = 0; e < NE; e++) p[e] += __shfl_xor_sync(0xffffffffu, p[e], o);
    if (lane == 0) {
#pragma unroll
        for (int e = 0; e < NE; e++) p[e] += bg[e];
        int i0 = 0;
#pragma unroll
        for (int e = 1; e < NE; e++) if (p[e] > p[i0]) i0 = e;
        int i1 = (i0 == 0) ? 1 : 0;
#pragma unroll
        for (int e = 0; e < NE; e++) if (e != i0 && p[e] > p[i1]) i1 = e;
        float w0 = 1.0f / (1.0f + expf(p[i1] - p[i0]));
        float w1 = 1.0f - w0;
        g_pw[2 * n + 0] = w0;
        g_pw[2 * n + 1] = w1;
        atomicAdd(&usage[i0], w0);
        atomicAdd(&usage[i1], w1);
        int q0 = atomicAdd(&g_cnt[i0], 1); g_list[i0 * NPAIR + q0] = 2 * n;
        int q1 = atomicAdd(&g_cnt[i1], 1); g_list[i1 * NPAIR + q1] = 2 * n + 1;
    }
}

// ---------------- grouped GEMM via wmma (bf16 hi/lo x3, fp32 accum) ---------
// D[m,n] = sum_k A[m,k] * B[k,n] + bias[n]
// A: gathered rows via g_list (row = pid>>ROWSH), K-major [*, KTOT]
// B: [E][KTOT][NTOT] row-major (original weight layout, split to bf16)
// SPLIT_OUT: emit hi/lo bf16 (fc1), else fp32 (fc2).
// All scratch pointers arrive as DEVICE-code values from the wrappers.
template<int KTOT, int NTOT, int ROWSH, bool SPLIT_OUT>
__device__ __forceinline__ void gemm_body(
        const __nv_bfloat16* Ahi, const __nv_bfloat16* Alo,
        const __nv_bfloat16* Bhi, const __nv_bfloat16* Blo,
        const float* __restrict__ bias,
        __nv_bfloat16* Ohi, __nv_bfloat16* Olo, float* Ofp) {
    constexpr int NCH = KTOT / BK;
    static __shared__ __align__(16) char sm[SM_BYTES];

    const int e   = blockIdx.z;
    const int cnt = g_cnt[e];
    const int m0  = blockIdx.y * M_T;
    if (m0 >= cnt) return;
    const int n0  = blockIdx.x * N_T;
    const int tid  = threadIdx.x;
    const int wid  = tid >> 5;
    const int lane = tid & 31;
    const int wm = wid & 3;        // 4 warps along M: 32 rows each
    const int wn = wid >> 2;       // 2 warps along N: 64 cols each

    // ---- loader setup: thread owns 2 segs of A-tile and 2 segs of B-tile ---
    const int s0 = tid, s1 = tid + 256;
    const int ar0 = s0 >> 2, ac0 = (s0 & 3) * 16;
    const int ar1 = s1 >> 2, ac1 = (s1 & 3) * 16;
    int am0 = m0 + ar0; if (am0 >= cnt) am0 = m0;     // duplicate; discarded
    int am1 = m0 + ar1; if (am1 >= cnt) am1 = m0;
    const size_t ao0 = (size_t)(g_list[e * NPAIR + am0] >> ROWSH) * (KTOT * 2);
    const size_t ao1 = (size_t)(g_list[e * NPAIR + am1] >> ROWSH) * (KTOT * 2);
    const uint32_t dA0 = (uint32_t)(ar0 * (ALD * 2) + ac0);
    const uint32_t dA1 = (uint32_t)(ar1 * (ALD * 2) + ac1);
    const int bk0 = s0 >> 4, bc0 = (s0 & 15) * 16;
    const int bk1 = s1 >> 4, bc1 = (s1 & 15) * 16;
    const size_t bo0 = (((size_t)e * KTOT + bk0) * NTOT + n0) * 2 + bc0;
    const size_t bo1 = (((size_t)e * KTOT + bk1) * NTOT + n0) * 2 + bc1;
    const uint32_t dB0 = (uint32_t)(bk0 * (BLD * 2) + bc0);
    const uint32_t dB1 = (uint32_t)(bk1 * (BLD * 2) + bc1);
    const char* pAh = (const char*)Ahi;
    const char* pAl = (const char*)Alo;
    const char* pBh = (const char*)Bhi;
    const char* pBl = (const char*)Blo;

    wmma::fragment<wmma::accumulator, 16, 16, 16, float> acc[2][4];
#pragma unroll
    for (int mi = 0; mi < 2; mi++)
#pragma unroll
        for (int nj = 0; nj < 4; nj++) wmma::fill_fragment(acc[mi][nj], 0.0f);

    const __nv_bfloat16* sAh = (const __nv_bfloat16*)(sm + SA_H);
    const __nv_bfloat16* sAl = (const __nv_bfloat16*)(sm + SA_L);
    const __nv_bfloat16* sBh = (const __nv_bfloat16*)(sm + SB_H);
    const __nv_bfloat16* sBl = (const __nv_bfloat16*)(sm + SB_L);

    for (int c = 0; c < NCH; c++) {
        __syncthreads();                       // previous compute done
        {
            const size_t ga = (size_t)c * (BK * 2);        // A: +64B per chunk
            const size_t gb = (size_t)c * (BK * NTOT * 2); // B: +32 k-rows
            *(uint4*)(sm + SA_H + dA0) = *(const uint4*)(pAh + ao0 + ga + ac0);
            *(uint4*)(sm + SA_H + dA1) = *(const uint4*)(pAh + ao1 + ga + ac1);
            *(uint4*)(sm + SA_L + dA0) = *(const uint4*)(pAl + ao0 + ga + ac0);
            *(uint4*)(sm + SA_L + dA1) = *(const uint4*)(pAl + ao1 + ga + ac1);
            *(uint4*)(sm + SB_H + dB0) = *(const uint4*)(pBh + bo0 + gb);
            *(uint4*)(sm + SB_H + dB1) = *(const uint4*)(pBh + bo1 + gb);
            *(uint4*)(sm + SB_L + dB0) = *(const uint4*)(pBl + bo0 + gb);
            *(uint4*)(sm + SB_L + dB1) = *(const uint4*)(pBl + bo1 + gb);
        }
        __syncthreads();
#pragma unroll
        for (int ks = 0; ks < 2; ks++) {
            wmma::fragment<wmma::matrix_a, 16, 16, 16, __nv_bfloat16,
                           wmma::row_major> ah[2], al[2];
#pragma unroll
            for (int mi = 0; mi < 2; mi++) {
                const int ro = (wm * 32 + mi * 16) * ALD + ks * 16;
                wmma::load_matrix_sync(ah[mi], sAh + ro, ALD);
                wmma::load_matrix_sync(al[mi], sAl + ro, ALD);
            }
#pragma unroll
            for (int nj = 0; nj < 4; nj++) {
                wmma::fragment<wmma::matrix_b, 16, 16, 16, __nv_bfloat16,
                               wmma::row_major> bh, bl;
                const int bo = (ks * 16) * BLD + wn * 64 + nj * 16;
                wmma::load_matrix_sync(bh, sBh + bo, BLD);
                wmma::load_matrix_sync(bl, sBl + bo, BLD);
#pragma unroll
                for (int mi = 0; mi < 2; mi++) {
                    wmma::mma_sync(acc[mi][nj], ah[mi], bh, acc[mi][nj]);
                    wmma::mma_sync(acc[mi][nj], ah[mi], bl, acc[mi][nj]);
                    wmma::mma_sync(acc[mi][nj], al[mi], bh, acc[mi][nj]);
                }
            }
        }
    }
    __syncthreads();                            // done with tiles; reuse as cs

    // ---- epilogue: per-warp 16x16 fp32 staging (pitch 20) ------------------
    float* cs = reinterpret_cast<float*>(sm + wid * (16 * 20 * 4));
    const int r  = lane >> 1;
    const int c0 = (lane & 1) * 8;
#pragma unroll
    for (int mi = 0; mi < 2; mi++) {
#pragma unroll
        for (int nj = 0; nj < 4; nj++) {
            wmma::store_matrix_sync(cs, acc[mi][nj], 20, wmma::mem_row_major);
            __syncwarp();
            const int m = m0 + wm * 32 + mi * 16 + r;
            if (m < cnt) {
                const int pid = g_list[e * NPAIR + m];
                const int nc  = n0 + wn * 64 + nj * 16 + c0;
                const float* bp = bias + (size_t)e * NTOT + nc;
                const float* cp = cs + r * 20 + c0;
                if (SPLIT_OUT) {
                    __nv_bfloat16* oh = Ohi + (size_t)pid * NTOT + nc;
                    __nv_bfloat16* ol = Olo + (size_t)pid * NTOT + nc;
#pragma unroll
                    for (int p = 0; p < 4; p++) {
                        float v0 = cp[2 * p + 0] + bp[2 * p + 0];
                        float v1 = cp[2 * p + 1] + bp[2 * p + 1];
                        __nv_bfloat16 h0 = __float2bfloat16(v0);
                        __nv_bfloat16 h1 = __float2bfloat16(v1);
                        *(__nv_bfloat162*)(oh + 2 * p) = __halves2bfloat162(h0, h1);
                        *(__nv_bfloat162*)(ol + 2 * p) = __halves2bfloat162(
                            __float2bfloat16(v0 - __bfloat162float(h0)),
                            __float2bfloat16(v1 - __bfloat162float(h1)));
                    }
                } else {
                    float* op = Ofp + (size_t)pid * NTOT + nc;
                    float4 w0, w1;
                    w0.x = cp[0] + bp[0]; w0.y = cp[1] + bp[1];
                    w0.z = cp[2] + bp[2]; w0.w = cp[3] + bp[3];
                    w1.x = cp[4] + bp[4]; w1.y = cp[5] + bp[5];
                    w1.z = cp[6] + bp[6]; w1.w = cp[7] + bp[7];
                    *(float4*)(op + 0) = w0;
                    *(float4*)(op + 4) = w1;
                }
            }
            __syncwarp();                       // before cs is overwritten
        }
    }
}

// Concrete wrappers: globals referenced from DEVICE code (correct addresses).
__global__ void __launch_bounds__(256) k_fc1g(const float* __restrict__ b1) {
    gemm_body<DIM, HID, 1, true>(g_xhi, g_xlo, g_w1hi, g_w1lo, b1,
                                 g_Hhi, g_Hlo, nullptr);
}
__global__ void __launch_bounds__(256) k_fc2g(const float* __restrict__ b2) {
    gemm_body<HID, DIM, 0, false>(g_Hhi, g_Hlo, g_w2hi, g_w2lo, b2,
                                  nullptr, nullptr, g_O);
}

// ---------------- combine ----------------------------------------------------
__global__ void k_comb(float* __restrict__ out) {
    int idx = blockIdx.x * blockDim.x + threadIdx.x;
    if (idx >= N_TOK * DIM / 4) return;
    int n  = idx / (DIM / 4);
    int d4 = idx % (DIM / 4);
    float w0 = g_pw[2 * n + 0];
    float w1 = g_pw[2 * n + 1];
    float4 a = *(const float4*)(g_O + (size_t)(2 * n + 0) * DIM + d4 * 4);
    float4 b = *(const float4*)(g_O + (size_t)(2 * n + 1) * DIM + d4 * 4);
    float4 r;
    r.x = w0 * a.x + w1 * b.x;
    r.y = w0 * a.y + w1 * b.y;
    r.z = w0 * a.z + w1 * b.z;
    r.w = w0 * a.w + w1 * b.w;
    *(float4*)(out + (size_t)idx * 4) = r;
}

// ---------------------------------------------------------------------------
extern "C" void kernel_launch(void* const* d_in, const int* in_sizes, int n_in,
                              void* d_out, int out_size) {
    const float* x  = (const float*)d_in[0];
    const float* Wg = (const float*)d_in[1];
    const float* bg = (const float*)d_in[2];
    const float* W1 = (const float*)d_in[3];
    const float* b1 = (const float*)d_in[4];
    const float* W2 = (const float*)d_in[5];
    const float* b2 = (const float*)d_in[6];
    float* out   = (float*)d_out;
    float* usage = out + (size_t)N_TOK * DIM;

    k_zero<<<1, 32>>>(usage);
    k_split_x<<<(N_TOK * DIM / 4 + 255) / 256, 256>>>(x);
    k_split_w1<<<(NE * DIM * HID / 4 + 255) / 256, 256>>>(W1);
    k_split_w2<<<(NE * HID * DIM / 4 + 255) / 256, 256>>>(W2);
    k_gate<<<N_TOK / 4, 128>>>(x, Wg, bg, usage);
    k_fc1g<<<dim3(HID / N_T, NPAIR / M_T, NE), 256>>>(b1);
    k_fc2g<<<dim3(DIM / N_T, NPAIR / M_T, NE), 256>>>(b2);
    k_comb<<<(N_TOK * DIM / 4) / 256, 256>>>(out);
}

// round 7
// speedup vs baseline: 1.9280x; 1.1415x over previous
#include <cuda_runtime.h>
#include <cuda_bf16.h>
#include <mma.h>
#include <cstdint>

using namespace nvcuda;

#define N_TOK 4096
#define DIM   512
#define HID   2048
#define NE    8
#define NPAIR (N_TOK * 2)

// GEMM tiling: CTA 128x128, BK=32, 256 threads (8 warps), warp tile 32x64
#define M_T 128
#define N_T 128
#define BK  32

// smem pitches (elements): A rows 40 (80B), B rows 136 (272B); both mult of 8
#define ALD 40
#define BLD 136
static constexpr int SA_H = 0;              // 128*40*2 = 10240
static constexpr int SA_L = 10240;
static constexpr int SB_H = 20480;          // 32*136*2 = 8704
static constexpr int SB_L = 29184;
static constexpr int STG  = 37888;          // one pipeline stage
static constexpr int NSTG = 3;
static constexpr int SMEM_DYN = NSTG * STG; // 113664 B (opt-in)

// ---------------- scratch (static device memory; device-code access ONLY) ---
// NOTE: never pass these as kernel arguments from host — host code sees the
// host *shadow* symbol, not the device address (silent corruption via ATS).
__device__ __align__(256) __nv_bfloat16 g_xhi[(size_t)N_TOK * DIM];
__device__ __align__(256) __nv_bfloat16 g_xlo[(size_t)N_TOK * DIM];
__device__ __align__(256) __nv_bfloat16 g_w1hi[(size_t)NE * DIM * HID];
__device__ __align__(256) __nv_bfloat16 g_w1lo[(size_t)NE * DIM * HID];
__device__ __align__(256) __nv_bfloat16 g_w2hi[(size_t)NE * HID * DIM];
__device__ __align__(256) __nv_bfloat16 g_w2lo[(size_t)NE * HID * DIM];
__device__ __align__(256) __nv_bfloat16 g_Hhi[(size_t)NPAIR * HID];
__device__ __align__(256) __nv_bfloat16 g_Hlo[(size_t)NPAIR * HID];
__device__ __align__(256) float g_O[(size_t)NPAIR * DIM];
__device__ __align__(256) float g_pw[NPAIR];
__device__ __align__(256) int   g_list[NE * NPAIR];
__device__ int g_cnt[NE];

// ---------------- PTX helpers ------------------------------------------------
__device__ __forceinline__ uint32_t smem_u32(const void* p) {
    uint32_t a;
    asm("{ .reg .u64 t; cvta.to.shared.u64 t, %1; cvt.u32.u64 %0, t; }"
        : "=r"(a) : "l"(p));
    return a;
}
__device__ __forceinline__ void cpa16(uint32_t s, const void* g) {
    asm volatile("cp.async.cg.shared.global [%0], [%1], 16;"
                 :: "r"(s), "l"(g) : "memory");
}
__device__ __forceinline__ void cpa_commit() {
    asm volatile("cp.async.commit_group;" ::: "memory");
}
template<int N>
__device__ __forceinline__ void cpa_wait() {
    asm volatile("cp.async.wait_group %0;" :: "n"(N) : "memory");
}

// ---------------- aux kernels ------------------------------------------------
__global__ void k_zero(float* __restrict__ usage) {
    int t = threadIdx.x;
    if (t < NE) { g_cnt[t] = 0; usage[t] = 0.0f; }
}

// fp32 -> bf16 hi/lo split body; wrappers pass globals from DEVICE code.
__device__ __forceinline__ void split_body(const float* __restrict__ src,
                                           __nv_bfloat16* hi,
                                           __nv_bfloat16* lo, int n4) {
    int i = blockIdx.x * blockDim.x + threadIdx.x;
    if (i >= n4) return;
    float4 v = ((const float4*)src)[i];
    __nv_bfloat16 h0 = __float2bfloat16(v.x), h1 = __float2bfloat16(v.y);
    __nv_bfloat16 h2 = __float2bfloat16(v.z), h3 = __float2bfloat16(v.w);
    ((__nv_bfloat162*)hi)[i * 2 + 0] = __halves2bfloat162(h0, h1);
    ((__nv_bfloat162*)hi)[i * 2 + 1] = __halves2bfloat162(h2, h3);
    ((__nv_bfloat162*)lo)[i * 2 + 0] = __halves2bfloat162(
        __float2bfloat16(v.x - __bfloat162float(h0)),
        __float2bfloat16(v.y - __bfloat162float(h1)));
    ((__nv_bfloat162*)lo)[i * 2 + 1] = __halves2bfloat162(
        __float2bfloat16(v.z - __bfloat162float(h2)),
        __float2bfloat16(v.w - __bfloat162float(h3)));
}

__global__ void k_split_x(const float* __restrict__ src) {
    split_body(src, g_xhi, g_xlo, N_TOK * DIM / 4);
}
__global__ void k_split_w1(const float* __restrict__ src) {
    split_body(src, g_w1hi, g_w1lo, NE * DIM * HID / 4);
}
__global__ void k_split_w2(const float* __restrict__ src) {
    split_body(src, g_w2hi, g_w2lo, NE * HID * DIM / 4);
}

__global__ void k_gate(const float* __restrict__ x,
                       const float* __restrict__ Wg,
                       const float* __restrict__ bg,
                       float* __restrict__ usage) {
    int n    = blockIdx.x * (blockDim.x >> 5) + (threadIdx.x >> 5);
    int lane = threadIdx.x & 31;
    if (n >= N_TOK) return;
    float p[NE];
#pragma unroll
    for (int e = 0; e < NE; e++) p[e] = 0.0f;
    const float* xr = x + (size_t)n * DIM;
    for (int d = lane; d < DIM; d += 32) {
        float xv = xr[d];
        const float* wr = Wg + (size_t)d * NE;
#pragma unroll
        for (int e = 0; e < NE; e++) p[e] = fmaf(xv, wr[e], p[e]);
    }
#pragma unroll
    for (int o = 16; o; o >>= 1)
#pragma unroll
        for (int e = 0; e < NE; e++) p[e] += __shfl_xor_sync(0xffffffffu, p[e], o);
    if (lane == 0) {
#pragma unroll
        for (int e = 0; e < NE; e++) p[e] += bg[e];
        int i0 = 0;
#pragma unroll
        for (int e = 1; e < NE; e++) if (p[e] > p[i0]) i0 = e;
        int i1 = (i0 == 0) ? 1 : 0;
#pragma unroll
        for (int e = 0; e < NE; e++) if (e != i0 && p[e] > p[i1]) i1 = e;
        float w0 = 1.0f / (1.0f + expf(p[i1] - p[i0]));
        float w1 = 1.0f - w0;
        g_pw[2 * n + 0] = w0;
        g_pw[2 * n + 1] = w1;
        atomicAdd(&usage[i0], w0);
        atomicAdd(&usage[i1], w1);
        int q0 = atomicAdd(&g_cnt[i0], 1); g_list[i0 * NPAIR + q0] = 2 * n;
        int q1 = atomicAdd(&g_cnt[i1], 1); g_list[i1 * NPAIR + q1] = 2 * n + 1;
    }
}

// ---------------- grouped GEMM via wmma + 3-stage cp.async pipeline ---------
// D[m,n] = sum_k A[m,k] * B[k,n] + bias[n]
// A: gathered rows via g_list (row = pid>>ROWSH), K-major [*, KTOT]
// B: [E][KTOT][NTOT] row-major.  SPLIT_OUT: emit hi/lo bf16 (fc1) else fp32.
template<int KTOT, int NTOT, int ROWSH, bool SPLIT_OUT>
__device__ __forceinline__ void gemm_body(
        const __nv_bfloat16* Ahi, const __nv_bfloat16* Alo,
        const __nv_bfloat16* Bhi, const __nv_bfloat16* Blo,
        const float* __restrict__ bias,
        __nv_bfloat16* Ohi, __nv_bfloat16* Olo, float* Ofp) {
    constexpr int NCH = KTOT / BK;
    extern __shared__ __align__(16) char sm[];

    const int e   = blockIdx.z;
    const int cnt = g_cnt[e];
    const int m0  = blockIdx.y * M_T;
    if (m0 >= cnt) return;
    const int n0  = blockIdx.x * N_T;
    const int tid  = threadIdx.x;
    const int wid  = tid >> 5;
    const int lane = tid & 31;
    const int wm = wid & 3;        // 4 warps along M: 32 rows each
    const int wn = wid >> 2;       // 2 warps along N: 64 cols each

    const uint32_t sb = smem_u32(sm);

    // ---- loader setup: thread owns 2 segs of A-tile and 2 segs of B-tile ---
    const int s0 = tid, s1 = tid + 256;
    const int ar0 = s0 >> 2, ac0 = (s0 & 3) * 16;
    const int ar1 = s1 >> 2, ac1 = (s1 & 3) * 16;
    int am0 = m0 + ar0; if (am0 >= cnt) am0 = m0;     // duplicate; discarded
    int am1 = m0 + ar1; if (am1 >= cnt) am1 = m0;
    const size_t ao0 = (size_t)(g_list[e * NPAIR + am0] >> ROWSH) * (KTOT * 2);
    const size_t ao1 = (size_t)(g_list[e * NPAIR + am1] >> ROWSH) * (KTOT * 2);
    const uint32_t dA0 = (uint32_t)(ar0 * (ALD * 2) + ac0);
    const uint32_t dA1 = (uint32_t)(ar1 * (ALD * 2) + ac1);
    const int bk0 = s0 >> 4, bc0 = (s0 & 15) * 16;
    const int bk1 = s1 >> 4, bc1 = (s1 & 15) * 16;
    const size_t bo0 = (((size_t)e * KTOT + bk0) * NTOT + n0) * 2 + bc0;
    const size_t bo1 = (((size_t)e * KTOT + bk1) * NTOT + n0) * 2 + bc1;
    const uint32_t dB0 = (uint32_t)(bk0 * (BLD * 2) + bc0);
    const uint32_t dB1 = (uint32_t)(bk1 * (BLD * 2) + bc1);
    const char* pAh = (const char*)Ahi;
    const char* pAl = (const char*)Alo;
    const char* pBh = (const char*)Bhi;
    const char* pBl = (const char*)Blo;

    auto issue = [&](int c) {
        const uint32_t st = sb + (uint32_t)(c % NSTG) * STG;
        const size_t ga = (size_t)c * (BK * 2);        // A: +64B per chunk
        const size_t gb = (size_t)c * (BK * NTOT * 2); // B: +32 k-rows
        cpa16(st + SA_H + dA0, pAh + ao0 + ga + ac0);
        cpa16(st + SA_H + dA1, pAh + ao1 + ga + ac1);
        cpa16(st + SA_L + dA0, pAl + ao0 + ga + ac0);
        cpa16(st + SA_L + dA1, pAl + ao1 + ga + ac1);
        cpa16(st + SB_H + dB0, pBh + bo0 + gb);
        cpa16(st + SB_H + dB1, pBh + bo1 + gb);
        cpa16(st + SB_L + dB0, pBl + bo0 + gb);
        cpa16(st + SB_L + dB1, pBl + bo1 + gb);
        cpa_commit();
    };

    wmma::fragment<wmma::accumulator, 16, 16, 16, float> acc[2][4];
#pragma unroll
    for (int mi = 0; mi < 2; mi++)
#pragma unroll
        for (int nj = 0; nj < 4; nj++) wmma::fill_fragment(acc[mi][nj], 0.0f);

    issue(0);
    issue(1);                                  // NCH >= 16 always
    for (int c = 0; c < NCH; c++) {
        if (c + 2 < NCH) { issue(c + 2); cpa_wait<2>(); }
        else if (c + 1 < NCH) { cpa_wait<1>(); }
        else { cpa_wait<0>(); }
        __syncthreads();                       // stage c visible to all warps

        const char* stg = sm + (size_t)(c % NSTG) * STG;
        const __nv_bfloat16* sAh = (const __nv_bfloat16*)(stg + SA_H);
        const __nv_bfloat16* sAl = (const __nv_bfloat16*)(stg + SA_L);
        const __nv_bfloat16* sBh = (const __nv_bfloat16*)(stg + SB_H);
        const __nv_bfloat16* sBl = (const __nv_bfloat16*)(stg + SB_L);
#pragma unroll
        for (int ks = 0; ks < 2; ks++) {
            wmma::fragment<wmma::matrix_a, 16, 16, 16, __nv_bfloat16,
                           wmma::row_major> ah[2], al[2];
#pragma unroll
            for (int mi = 0; mi < 2; mi++) {
                const int ro = (wm * 32 + mi * 16) * ALD + ks * 16;
                wmma::load_matrix_sync(ah[mi], sAh + ro, ALD);
                wmma::load_matrix_sync(al[mi], sAl + ro, ALD);
            }
#pragma unroll
            for (int nj = 0; nj < 4; nj++) {
                wmma::fragment<wmma::matrix_b, 16, 16, 16, __nv_bfloat16,
                               wmma::row_major> bh, bl;
                const int bo = (ks * 16) * BLD + wn * 64 + nj * 16;
                wmma::load_matrix_sync(bh, sBh + bo, BLD);
                wmma::load_matrix_sync(bl, sBl + bo, BLD);
#pragma unroll
                for (int mi = 0; mi < 2; mi++) {
                    wmma::mma_sync(acc[mi][nj], ah[mi], bh, acc[mi][nj]);
                    wmma::mma_sync(acc[mi][nj], ah[mi], bl, acc[mi][nj]);
                    wmma::mma_sync(acc[mi][nj], al[mi], bh, acc[mi][nj]);
                }
            }
        }
        __syncthreads();                       // stage safe for reuse at c+NSTG
    }

    // ---- epilogue: per-warp 16x16 fp32 staging (pitch 20) ------------------
    float* cs = reinterpret_cast<float*>(sm + wid * (16 * 20 * 4));
    const int r  = lane >> 1;
    const int c0 = (lane & 1) * 8;
#pragma unroll
    for (int mi = 0; mi < 2; mi++) {
#pragma unroll
        for (int nj = 0; nj < 4; nj++) {
            wmma::store_matrix_sync(cs, acc[mi][nj], 20, wmma::mem_row_major);
            __syncwarp();
            const int m = m0 + wm * 32 + mi * 16 + r;
            if (m < cnt) {
                const int pid = g_list[e * NPAIR + m];
                const int nc  = n0 + wn * 64 + nj * 16 + c0;
                const float* bp = bias + (size_t)e * NTOT + nc;
                const float* cp = cs + r * 20 + c0;
                if (SPLIT_OUT) {
                    __nv_bfloat16* oh = Ohi + (size_t)pid * NTOT + nc;
                    __nv_bfloat16* ol = Olo + (size_t)pid * NTOT + nc;
#pragma unroll
                    for (int p = 0; p < 4; p++) {
                        float v0 = cp[2 * p + 0] + bp[2 * p + 0];
                        float v1 = cp[2 * p + 1] + bp[2 * p + 1];
                        __nv_bfloat16 h0 = __float2bfloat16(v0);
                        __nv_bfloat16 h1 = __float2bfloat16(v1);
                        *(__nv_bfloat162*)(oh + 2 * p) = __halves2bfloat162(h0, h1);
                        *(__nv_bfloat162*)(ol + 2 * p) = __halves2bfloat162(
                            __float2bfloat16(v0 - __bfloat162float(h0)),
                            __float2bfloat16(v1 - __bfloat162float(h1)));
                    }
                } else {
                    float* op = Ofp + (size_t)pid * NTOT + nc;
                    float4 w0, w1;
                    w0.x = cp[0] + bp[0]; w0.y = cp[1] + bp[1];
                    w0.z = cp[2] + bp[2]; w0.w = cp[3] + bp[3];
                    w1.x = cp[4] + bp[4]; w1.y = cp[5] + bp[5];
                    w1.z = cp[6] + bp[6]; w1.w = cp[7] + bp[7];
                    *(float4*)(op + 0) = w0;
                    *(float4*)(op + 4) = w1;
                }
            }
            __syncwarp();                       // before cs is overwritten
        }
    }
}

// Concrete wrappers: globals referenced from DEVICE code (correct addresses).
__global__ void __launch_bounds__(256) k_fc1g(const float* __restrict__ b1) {
    gemm_body<DIM, HID, 1, true>(g_xhi, g_xlo, g_w1hi, g_w1lo, b1,
                                 g_Hhi, g_Hlo, nullptr);
}
__global__ void __launch_bounds__(256) k_fc2g(const float* __restrict__ b2) {
    gemm_body<HID, DIM, 0, false>(g_Hhi, g_Hlo, g_w2hi, g_w2lo, b2,
                                  nullptr, nullptr, g_O);
}

// ---------------- combine ----------------------------------------------------
__global__ void k_comb(float* __restrict__ out) {
    int idx = blockIdx.x * blockDim.x + threadIdx.x;
    if (idx >= N_TOK * DIM / 4) return;
    int n  = idx / (DIM / 4);
    int d4 = idx % (DIM / 4);
    float w0 = g_pw[2 * n + 0];
    float w1 = g_pw[2 * n + 1];
    float4 a = *(const float4*)(g_O + (size_t)(2 * n + 0) * DIM + d4 * 4);
    float4 b = *(const float4*)(g_O + (size_t)(2 * n + 1) * DIM + d4 * 4);
    float4 r;
    r.x = w0 * a.x + w1 * b.x;
    r.y = w0 * a.y + w1 * b.y;
    r.z = w0 * a.z + w1 * b.z;
    r.w = w0 * a.w + w1 * b.w;
    *(float4*)(out + (size_t)idx * 4) = r;
}

// ---------------------------------------------------------------------------
extern "C" void kernel_launch(void* const* d_in, const int* in_sizes, int n_in,
                              void* d_out, int out_size) {
    const float* x  = (const float*)d_in[0];
    const float* Wg = (const float*)d_in[1];
    const float* bg = (const float*)d_in[2];
    const float* W1 = (const float*)d_in[3];
    const float* b1 = (const float*)d_in[4];
    const float* W2 = (const float*)d_in[5];
    const float* b2 = (const float*)d_in[6];
    float* out   = (float*)d_out;
    float* usage = out + (size_t)N_TOK * DIM;

    cudaFuncSetAttribute(k_fc1g, cudaFuncAttributeMaxDynamicSharedMemorySize,
                         SMEM_DYN);
    cudaFuncSetAttribute(k_fc2g, cudaFuncAttributeMaxDynamicSharedMemorySize,
                         SMEM_DYN);

    k_zero<<<1, 32>>>(usage);
    k_split_x<<<(N_TOK * DIM / 4 + 255) / 256, 256>>>(x);
    k_split_w1<<<(NE * DIM * HID / 4 + 255) / 256, 256>>>(W1);
    k_split_w2<<<(NE * HID * DIM / 4 + 255) / 256, 256>>>(W2);
    k_gate<<<N_TOK / 4, 128>>>(x, Wg, bg, usage);
    k_fc1g<<<dim3(HID / N_T, NPAIR / M_T, NE), 256, SMEM_DYN>>>(b1);
    k_fc2g<<<dim3(DIM / N_T, NPAIR / M_T, NE), 256, SMEM_DYN>>>(b2);
    k_comb<<<(N_TOK * DIM / 4) / 256, 256>>>(out);
}

// round 8
// speedup vs baseline: 2.2410x; 1.1623x over previous
#include <cuda_runtime.h>
#include <cuda_bf16.h>
#include <mma.h>
#include <cstdint>

using namespace nvcuda;

#define N_TOK 4096
#define DIM   512
#define HID   2048
#define NE    8
#define NPAIR (N_TOK * 2)

// GEMM tiling: CTA 128x256, BK=32, 256 threads (8 warps 2x4), warp tile 64x64
#define M_T 128
#define N_T 256
#define BK  32

// smem pitches (elements): A rows 40 (80B), B rows 264 (528B)
#define ALD 40
#define BLD 264
static constexpr int SA_H = 0;               // 128*40*2  = 10240
static constexpr int SA_L = 10240;
static constexpr int SB_H = 20480;           // 32*264*2  = 16896
static constexpr int SB_L = 37376;
static constexpr int STG  = 54272;           // one pipeline stage
static constexpr int NSTG = 3;
static constexpr int SMEM_DYN = NSTG * STG;  // 162816 B (opt-in)

// ---------------- scratch (static device memory; device-code access ONLY) ---
// NOTE: never pass these as kernel arguments from host — host code sees the
// host *shadow* symbol, not the device address (silent corruption via ATS).
__device__ __align__(256) __nv_bfloat16 g_xhi[(size_t)N_TOK * DIM];
__device__ __align__(256) __nv_bfloat16 g_xlo[(size_t)N_TOK * DIM];
__device__ __align__(256) __nv_bfloat16 g_w1hi[(size_t)NE * DIM * HID];
__device__ __align__(256) __nv_bfloat16 g_w1lo[(size_t)NE * DIM * HID];
__device__ __align__(256) __nv_bfloat16 g_w2hi[(size_t)NE * HID * DIM];
__device__ __align__(256) __nv_bfloat16 g_w2lo[(size_t)NE * HID * DIM];
__device__ __align__(256) __nv_bfloat16 g_Hhi[(size_t)NPAIR * HID];
__device__ __align__(256) __nv_bfloat16 g_Hlo[(size_t)NPAIR * HID];
__device__ __align__(256) float g_O[(size_t)NPAIR * DIM];
__device__ __align__(256) float g_pw[NPAIR];
__device__ __align__(256) int   g_list[NE * NPAIR];
__device__ int g_cnt[NE];

// ---------------- PTX helpers ------------------------------------------------
__device__ __forceinline__ uint32_t smem_u32(const void* p) {
    uint32_t a;
    asm("{ .reg .u64 t; cvta.to.shared.u64 t, %1; cvt.u32.u64 %0, t; }"
        : "=r"(a) : "l"(p));
    return a;
}
__device__ __forceinline__ void cpa16(uint32_t s, const void* g) {
    asm volatile("cp.async.cg.shared.global [%0], [%1], 16;"
                 :: "r"(s), "l"(g) : "memory");
}
__device__ __forceinline__ void cpa_commit() {
    asm volatile("cp.async.commit_group;" ::: "memory");
}
template<int N>
__device__ __forceinline__ void cpa_wait() {
    asm volatile("cp.async.wait_group %0;" :: "n"(N) : "memory");
}

// ---------------- aux kernels ------------------------------------------------
__global__ void k_zero(float* __restrict__ usage) {
    int t = threadIdx.x;
    if (t < NE) { g_cnt[t] = 0; usage[t] = 0.0f; }
}

// fp32 -> bf16 hi/lo split body; wrappers pass globals from DEVICE code.
__device__ __forceinline__ void split_body(const float* __restrict__ src,
                                           __nv_bfloat16* hi,
                                           __nv_bfloat16* lo, int n4) {
    int i = blockIdx.x * blockDim.x + threadIdx.x;
    if (i >= n4) return;
    float4 v = ((const float4*)src)[i];
    __nv_bfloat16 h0 = __float2bfloat16(v.x), h1 = __float2bfloat16(v.y);
    __nv_bfloat16 h2 = __float2bfloat16(v.z), h3 = __float2bfloat16(v.w);
    ((__nv_bfloat162*)hi)[i * 2 + 0] = __halves2bfloat162(h0, h1);
    ((__nv_bfloat162*)hi)[i * 2 + 1] = __halves2bfloat162(h2, h3);
    ((__nv_bfloat162*)lo)[i * 2 + 0] = __halves2bfloat162(
        __float2bfloat16(v.x - __bfloat162float(h0)),
        __float2bfloat16(v.y - __bfloat162float(h1)));
    ((__nv_bfloat162*)lo)[i * 2 + 1] = __halves2bfloat162(
        __float2bfloat16(v.z - __bfloat162float(h2)),
        __float2bfloat16(v.w - __bfloat162float(h3)));
}

__global__ void k_split_x(const float* __restrict__ src) {
    split_body(src, g_xhi, g_xlo, N_TOK * DIM / 4);
}
__global__ void k_split_w1(const float* __restrict__ src) {
    split_body(src, g_w1hi, g_w1lo, NE * DIM * HID / 4);
}
__global__ void k_split_w2(const float* __restrict__ src) {
    split_body(src, g_w2hi, g_w2lo, NE * HID * DIM / 4);
}

__global__ void k_gate(const float* __restrict__ x,
                       const float* __restrict__ Wg,
                       const float* __restrict__ bg,
                       float* __restrict__ usage) {
    int n    = blockIdx.x * (blockDim.x >> 5) + (threadIdx.x >> 5);
    int lane = threadIdx.x & 31;
    if (n >= N_TOK) return;
    float p[NE];
#pragma unroll
    for (int e = 0; e < NE; e++) p[e] = 0.0f;
    const float* xr = x + (size_t)n * DIM;
    for (int d = lane; d < DIM; d += 32) {
        float xv = xr[d];
        const float* wr = Wg + (size_t)d * NE;
#pragma unroll
        for (int e = 0; e < NE; e++) p[e] = fmaf(xv, wr[e], p[e]);
    }
#pragma unroll
    for (int o = 16; o; o >>= 1)
#pragma unroll
        for (int e = 0; e < NE; e++) p[e] += __shfl_xor_sync(0xffffffffu, p[e], o);
    if (lane == 0) {
#pragma unroll
        for (int e = 0; e < NE; e++) p[e] += bg[e];
        int i0 = 0;
#pragma unroll
        for (int e = 1; e < NE; e++) if (p[e] > p[i0]) i0 = e;
        int i1 = (i0 == 0) ? 1 : 0;
#pragma unroll
        for (int e = 0; e < NE; e++) if (e != i0 && p[e] > p[i1]) i1 = e;
        float w0 = 1.0f / (1.0f + expf(p[i1] - p[i0]));
        float w1 = 1.0f - w0;
        g_pw[2 * n + 0] = w0;
        g_pw[2 * n + 1] = w1;
        atomicAdd(&usage[i0], w0);
        atomicAdd(&usage[i1], w1);
        int q0 = atomicAdd(&g_cnt[i0], 1); g_list[i0 * NPAIR + q0] = 2 * n;
        int q1 = atomicAdd(&g_cnt[i1], 1); g_list[i1 * NPAIR + q1] = 2 * n + 1;
    }
}

// ---------------- grouped GEMM via wmma + 3-stage cp.async pipeline ---------
// D[m,n] = sum_k A[m,k] * B[k,n] + bias[n]
// A: gathered rows via g_list (row = pid>>ROWSH), K-major [*, KTOT]
// B: [E][KTOT][NTOT] row-major.  SPLIT_OUT: emit hi/lo bf16 (fc1) else fp32.
template<int KTOT, int NTOT, int ROWSH, bool SPLIT_OUT>
__device__ __forceinline__ void gemm_body(
        const __nv_bfloat16* Ahi, const __nv_bfloat16* Alo,
        const __nv_bfloat16* Bhi, const __nv_bfloat16* Blo,
        const float* __restrict__ bias,
        __nv_bfloat16* Ohi, __nv_bfloat16* Olo, float* Ofp) {
    constexpr int NCH = KTOT / BK;
    extern __shared__ __align__(16) char sm[];

    const int e   = blockIdx.z;
    const int cnt = g_cnt[e];
    const int m0  = blockIdx.y * M_T;
    if (m0 >= cnt) return;
    const int n0  = blockIdx.x * N_T;
    const int tid  = threadIdx.x;
    const int wid  = tid >> 5;
    const int lane = tid & 31;
    const int wm = wid & 1;        // 2 warps along M: 64 rows each
    const int wn = wid >> 1;       // 4 warps along N: 64 cols each

    const uint32_t sb = smem_u32(sm);

    // ---- loader setup ------------------------------------------------------
    // A tile: 128 rows x 64B = 512 segs; thread owns segs tid, tid+256
    const int s0 = tid, s1 = tid + 256;
    const int ar0 = s0 >> 2, ac0 = (s0 & 3) * 16;
    const int ar1 = s1 >> 2, ac1 = (s1 & 3) * 16;
    int am0 = m0 + ar0; if (am0 >= cnt) am0 = m0;     // duplicate; discarded
    int am1 = m0 + ar1; if (am1 >= cnt) am1 = m0;
    const size_t ao0 = (size_t)(g_list[e * NPAIR + am0] >> ROWSH) * (KTOT * 2);
    const size_t ao1 = (size_t)(g_list[e * NPAIR + am1] >> ROWSH) * (KTOT * 2);
    const uint32_t dA0 = (uint32_t)(ar0 * (ALD * 2) + ac0);
    const uint32_t dA1 = (uint32_t)(ar1 * (ALD * 2) + ac1);
    // B tile: 32 k-rows x 512B = 1024 segs; thread owns tid + 256*j, j=0..3
    uint32_t dB[4];
    size_t   bo[4];
#pragma unroll
    for (int j = 0; j < 4; j++) {
        const int s  = tid + 256 * j;
        const int bk = s >> 5, bc = (s & 31) * 16;
        dB[j] = (uint32_t)(bk * (BLD * 2) + bc);
        bo[j] = (((size_t)e * KTOT + bk) * NTOT + n0) * 2 + bc;
    }
    const char* pAh = (const char*)Ahi;
    const char* pAl = (const char*)Alo;
    const char* pBh = (const char*)Bhi;
    const char* pBl = (const char*)Blo;

    auto issue = [&](int c) {
        const uint32_t st = sb + (uint32_t)(c % NSTG) * STG;
        const size_t ga = (size_t)c * (BK * 2);        // A: +64B per chunk
        const size_t gb = (size_t)c * (BK * NTOT * 2); // B: +32 k-rows
        cpa16(st + SA_H + dA0, pAh + ao0 + ga + ac0);
        cpa16(st + SA_H + dA1, pAh + ao1 + ga + ac1);
        cpa16(st + SA_L + dA0, pAl + ao0 + ga + ac0);
        cpa16(st + SA_L + dA1, pAl + ao1 + ga + ac1);
#pragma unroll
        for (int j = 0; j < 4; j++) {
            cpa16(st + SB_H + dB[j], pBh + bo[j] + gb);
            cpa16(st + SB_L + dB[j], pBl + bo[j] + gb);
        }
        cpa_commit();
    };

    wmma::fragment<wmma::accumulator, 16, 16, 16, float> acc[4][4];
#pragma unroll
    for (int mi = 0; mi < 4; mi++)
#pragma unroll
        for (int nj = 0; nj < 4; nj++) wmma::fill_fragment(acc[mi][nj], 0.0f);

    issue(0);
    issue(1);                                  // NCH >= 16 always
    for (int c = 0; c < NCH; c++) {
        if (c + 2 < NCH) { issue(c + 2); cpa_wait<2>(); }
        else if (c + 1 < NCH) { cpa_wait<1>(); }
        else { cpa_wait<0>(); }
        __syncthreads();                       // stage c visible to all warps

        const char* stg = sm + (size_t)(c % NSTG) * STG;
        const __nv_bfloat16* sAh = (const __nv_bfloat16*)(stg + SA_H);
        const __nv_bfloat16* sAl = (const __nv_bfloat16*)(stg + SA_L);
        const __nv_bfloat16* sBh = (const __nv_bfloat16*)(stg + SB_H);
        const __nv_bfloat16* sBl = (const __nv_bfloat16*)(stg + SB_L);
#pragma unroll
        for (int ks = 0; ks < 2; ks++) {
            wmma::fragment<wmma::matrix_a, 16, 16, 16, __nv_bfloat16,
                           wmma::row_major> ah[4], al[4];
#pragma unroll
            for (int mi = 0; mi < 4; mi++) {
                const int ro = (wm * 64 + mi * 16) * ALD + ks * 16;
                wmma::load_matrix_sync(ah[mi], sAh + ro, ALD);
                wmma::load_matrix_sync(al[mi], sAl + ro, ALD);
            }
#pragma unroll
            for (int nj = 0; nj < 4; nj++) {
                wmma::fragment<wmma::matrix_b, 16, 16, 16, __nv_bfloat16,
                               wmma::row_major> bh, bl;
                const int bo2 = (ks * 16) * BLD + wn * 64 + nj * 16;
                wmma::load_matrix_sync(bh, sBh + bo2, BLD);
                wmma::load_matrix_sync(bl, sBl + bo2, BLD);
#pragma unroll
                for (int mi = 0; mi < 4; mi++) {
                    wmma::mma_sync(acc[mi][nj], ah[mi], bh, acc[mi][nj]);
                    wmma::mma_sync(acc[mi][nj], ah[mi], bl, acc[mi][nj]);
                    wmma::mma_sync(acc[mi][nj], al[mi], bh, acc[mi][nj]);
                }
            }
        }
        __syncthreads();                       // stage safe for reuse at c+NSTG
    }

    // ---- epilogue: per-warp 16x16 fp32 staging (pitch 20) ------------------
    float* cs = reinterpret_cast<float*>(sm + wid * (16 * 20 * 4));
    const int r  = lane >> 1;
    const int c0 = (lane & 1) * 8;
#pragma unroll
    for (int mi = 0; mi < 4; mi++) {
#pragma unroll
        for (int nj = 0; nj < 4; nj++) {
            wmma::store_matrix_sync(cs, acc[mi][nj], 20, wmma::mem_row_major);
            __syncwarp();
            const int m = m0 + wm * 64 + mi * 16 + r;
            if (m < cnt) {
                const int pid = g_list[e * NPAIR + m];
                const int nc  = n0 + wn * 64 + nj * 16 + c0;
                const float* bp = bias + (size_t)e * NTOT + nc;
                const float* cp = cs + r * 20 + c0;
                if (SPLIT_OUT) {
                    __nv_bfloat16* oh = Ohi + (size_t)pid * NTOT + nc;
                    __nv_bfloat16* ol = Olo + (size_t)pid * NTOT + nc;
#pragma unroll
                    for (int p = 0; p < 4; p++) {
                        float v0 = cp[2 * p + 0] + bp[2 * p + 0];
                        float v1 = cp[2 * p + 1] + bp[2 * p + 1];
                        __nv_bfloat16 h0 = __float2bfloat16(v0);
                        __nv_bfloat16 h1 = __float2bfloat16(v1);
                        *(__nv_bfloat162*)(oh + 2 * p) = __halves2bfloat162(h0, h1);
                        *(__nv_bfloat162*)(ol + 2 * p) = __halves2bfloat162(
                            __float2bfloat16(v0 - __bfloat162float(h0)),
                            __float2bfloat16(v1 - __bfloat162float(h1)));
                    }
                } else {
                    float* op = Ofp + (size_t)pid * NTOT + nc;
                    float4 w0, w1;
                    w0.x = cp[0] + bp[0]; w0.y = cp[1] + bp[1];
                    w0.z = cp[2] + bp[2]; w0.w = cp[3] + bp[3];
                    w1.x = cp[4] + bp[4]; w1.y = cp[5] + bp[5];
                    w1.z = cp[6] + bp[6]; w1.w = cp[7] + bp[7];
                    *(float4*)(op + 0) = w0;
                    *(float4*)(op + 4) = w1;
                }
            }
            __syncwarp();                       // before cs is overwritten
        }
    }
}

// Concrete wrappers: globals referenced from DEVICE code (correct addresses).
__global__ void __launch_bounds__(256) k_fc1g(const float* __restrict__ b1) {
    gemm_body<DIM, HID, 1, true>(g_xhi, g_xlo, g_w1hi, g_w1lo, b1,
                                 g_Hhi, g_Hlo, nullptr);
}
__global__ void __launch_bounds__(256) k_fc2g(const float* __restrict__ b2) {
    gemm_body<HID, DIM, 0, false>(g_Hhi, g_Hlo, g_w2hi, g_w2lo, b2,
                                  nullptr, nullptr, g_O);
}

// ---------------- combine ----------------------------------------------------
__global__ void k_comb(float* __restrict__ out) {
    int idx = blockIdx.x * blockDim.x + threadIdx.x;
    if (idx >= N_TOK * DIM / 4) return;
    int n  = idx / (DIM / 4);
    int d4 = idx % (DIM / 4);
    float w0 = g_pw[2 * n + 0];
    float w1 = g_pw[2 * n + 1];
    float4 a = *(const float4*)(g_O + (size_t)(2 * n + 0) * DIM + d4 * 4);
    float4 b = *(const float4*)(g_O + (size_t)(2 * n + 1) * DIM + d4 * 4);
    float4 r;
    r.x = w0 * a.x + w1 * b.x;
    r.y = w0 * a.y + w1 * b.y;
    r.z = w0 * a.z + w1 * b.z;
    r.w = w0 * a.w + w1 * b.w;
    *(float4*)(out + (size_t)idx * 4) = r;
}

// ---------------------------------------------------------------------------
extern "C" void kernel_launch(void* const* d_in, const int* in_sizes, int n_in,
                              void* d_out, int out_size) {
    const float* x  = (const float*)d_in[0];
    const float* Wg = (const float*)d_in[1];
    const float* bg = (const float*)d_in[2];
    const float* W1 = (const float*)d_in[3];
    const float* b1 = (const float*)d_in[4];
    const float* W2 = (const float*)d_in[5];
    const float* b2 = (const float*)d_in[6];
    float* out   = (float*)d_out;
    float* usage = out + (size_t)N_TOK * DIM;

    cudaFuncSetAttribute(k_fc1g, cudaFuncAttributeMaxDynamicSharedMemorySize,
                         SMEM_DYN);
    cudaFuncSetAttribute(k_fc2g, cudaFuncAttributeMaxDynamicSharedMemorySize,
                         SMEM_DYN);

    k_zero<<<1, 32>>>(usage);
    k_split_x<<<(N_TOK * DIM / 4 + 255) / 256, 256>>>(x);
    k_split_w1<<<(NE * DIM * HID / 4 + 255) / 256, 256>>>(W1);
    k_split_w2<<<(NE * HID * DIM / 4 + 255) / 256, 256>>>(W2);
    k_gate<<<N_TOK / 4, 128>>>(x, Wg, bg, usage);
    k_fc1g<<<dim3(HID / N_T, NPAIR / M_T, NE), 256, SMEM_DYN>>>(b1);
    k_fc2g<<<dim3(DIM / N_T, NPAIR / M_T, NE), 256, SMEM_DYN>>>(b2);
    k_comb<<<(N_TOK * DIM / 4) / 256, 256>>>(out);
}

// round 9
// speedup vs baseline: 2.4726x; 1.1034x over previous
#include <cuda_runtime.h>
#include <cuda_bf16.h>
#include <mma.h>
#include <cstdint>

using namespace nvcuda;

#define N_TOK 4096
#define DIM   512
#define HID   2048
#define NE    8
#define NPAIR (N_TOK * 2)

// GEMM tiling: CTA 128x128, BK=32, 128 threads (4 warps 2x2), warp tile 64x64
#define M_T 128
#define N_T 128
#define BK  32

// smem pitches (elements): A rows 40 (80B), B rows 136 (272B)
#define ALD 40
#define BLD 136
static constexpr int SA_H = 0;               // 128*40*2 = 10240
static constexpr int SA_L = 10240;
static constexpr int SB_H = 20480;           // 32*136*2 = 8704
static constexpr int SB_L = 29184;
static constexpr int STG  = 37888;           // one pipeline stage
static constexpr int NSTG = 3;
static constexpr int SMEM_DYN = NSTG * STG;  // 113664 B -> 2 CTAs/SM

// ---------------- scratch (static device memory; device-code access ONLY) ---
// NOTE: never pass these as kernel arguments from host — host code sees the
// host *shadow* symbol, not the device address (silent corruption via ATS).
__device__ __align__(256) __nv_bfloat16 g_xhi[(size_t)N_TOK * DIM];
__device__ __align__(256) __nv_bfloat16 g_xlo[(size_t)N_TOK * DIM];
__device__ __align__(256) __nv_bfloat16 g_w1hi[(size_t)NE * DIM * HID];
__device__ __align__(256) __nv_bfloat16 g_w1lo[(size_t)NE * DIM * HID];
__device__ __align__(256) __nv_bfloat16 g_w2hi[(size_t)NE * HID * DIM];
__device__ __align__(256) __nv_bfloat16 g_w2lo[(size_t)NE * HID * DIM];
__device__ __align__(256) __nv_bfloat16 g_Hhi[(size_t)NPAIR * HID];
__device__ __align__(256) __nv_bfloat16 g_Hlo[(size_t)NPAIR * HID];
__device__ __align__(256) float g_O[(size_t)NPAIR * DIM];
__device__ __align__(256) float g_pw[NPAIR];
__device__ __align__(256) int   g_list[NE * NPAIR];
__device__ int g_cnt[NE];

// ---------------- PTX helpers ------------------------------------------------
__device__ __forceinline__ uint32_t smem_u32(const void* p) {
    uint32_t a;
    asm("{ .reg .u64 t; cvta.to.shared.u64 t, %1; cvt.u32.u64 %0, t; }"
        : "=r"(a) : "l"(p));
    return a;
}
__device__ __forceinline__ void cpa16(uint32_t s, const void* g) {
    asm volatile("cp.async.cg.shared.global [%0], [%1], 16;"
                 :: "r"(s), "l"(g) : "memory");
}
__device__ __forceinline__ void cpa_commit() {
    asm volatile("cp.async.commit_group;" ::: "memory");
}
template<int N>
__device__ __forceinline__ void cpa_wait() {
    asm volatile("cp.async.wait_group %0;" :: "n"(N) : "memory");
}

// ---------------- aux kernels ------------------------------------------------
__global__ void k_zero(float* __restrict__ usage) {
    int t = threadIdx.x;
    if (t < NE) { g_cnt[t] = 0; usage[t] = 0.0f; }
}

// fp32 -> bf16 hi/lo split body; wrappers pass globals from DEVICE code.
__device__ __forceinline__ void split_one(const float* __restrict__ src,
                                          __nv_bfloat16* hi,
                                          __nv_bfloat16* lo, int i) {
    float4 v = ((const float4*)src)[i];
    __nv_bfloat16 h0 = __float2bfloat16(v.x), h1 = __float2bfloat16(v.y);
    __nv_bfloat16 h2 = __float2bfloat16(v.z), h3 = __float2bfloat16(v.w);
    ((__nv_bfloat162*)hi)[i * 2 + 0] = __halves2bfloat162(h0, h1);
    ((__nv_bfloat162*)hi)[i * 2 + 1] = __halves2bfloat162(h2, h3);
    ((__nv_bfloat162*)lo)[i * 2 + 0] = __halves2bfloat162(
        __float2bfloat16(v.x - __bfloat162float(h0)),
        __float2bfloat16(v.y - __bfloat162float(h1)));
    ((__nv_bfloat162*)lo)[i * 2 + 1] = __halves2bfloat162(
        __float2bfloat16(v.z - __bfloat162float(h2)),
        __float2bfloat16(v.w - __bfloat162float(h3)));
}

__global__ void k_split_x(const float* __restrict__ src) {
    int i = blockIdx.x * blockDim.x + threadIdx.x;
    if (i < N_TOK * DIM / 4) split_one(src, g_xhi, g_xlo, i);
}
// fused W1+W2 split: one launch for both weight tensors
__global__ void k_split_w(const float* __restrict__ W1,
                          const float* __restrict__ W2) {
    constexpr int W_N4 = NE * DIM * HID / 4;
    int i = blockIdx.x * blockDim.x + threadIdx.x;
    if (i < W_N4)              split_one(W1, g_w1hi, g_w1lo, i);
    else if (i < 2 * W_N4)     split_one(W2, g_w2hi, g_w2lo, i - W_N4);
}

__global__ void k_gate(const float* __restrict__ x,
                       const float* __restrict__ Wg,
                       const float* __restrict__ bg,
                       float* __restrict__ usage) {
    int n    = blockIdx.x * (blockDim.x >> 5) + (threadIdx.x >> 5);
    int lane = threadIdx.x & 31;
    if (n >= N_TOK) return;
    float p[NE];
#pragma unroll
    for (int e = 0; e < NE; e++) p[e] = 0.0f;
    const float* xr = x + (size_t)n * DIM;
    for (int d = lane; d < DIM; d += 32) {
        float xv = xr[d];
        const float* wr = Wg + (size_t)d * NE;
#pragma unroll
        for (int e = 0; e < NE; e++) p[e] = fmaf(xv, wr[e], p[e]);
    }
#pragma unroll
    for (int o = 16; o; o >>= 1)
#pragma unroll
        for (int e = 0; e < NE; e++) p[e] += __shfl_xor_sync(0xffffffffu, p[e], o);
    if (lane == 0) {
#pragma unroll
        for (int e = 0; e < NE; e++) p[e] += bg[e];
        int i0 = 0;
#pragma unroll
        for (int e = 1; e < NE; e++) if (p[e] > p[i0]) i0 = e;
        int i1 = (i0 == 0) ? 1 : 0;
#pragma unroll
        for (int e = 0; e < NE; e++) if (e != i0 && p[e] > p[i1]) i1 = e;
        float w0 = 1.0f / (1.0f + expf(p[i1] - p[i0]));
        float w1 = 1.0f - w0;
        g_pw[2 * n + 0] = w0;
        g_pw[2 * n + 1] = w1;
        atomicAdd(&usage[i0], w0);
        atomicAdd(&usage[i1], w1);
        int q0 = atomicAdd(&g_cnt[i0], 1); g_list[i0 * NPAIR + q0] = 2 * n;
        int q1 = atomicAdd(&g_cnt[i1], 1); g_list[i1 * NPAIR + q1] = 2 * n + 1;
    }
}

// ---------------- grouped GEMM via wmma + 3-stage cp.async pipeline ---------
// D[m,n] = sum_k A[m,k] * B[k,n] + bias[n]
// A: gathered rows via g_list (row = pid>>ROWSH), K-major [*, KTOT]
// B: [E][KTOT][NTOT] row-major.  SPLIT_OUT: emit hi/lo bf16 (fc1) else fp32.
// 128 threads, 4 warps (2x2), warp tile 64x64.
template<int KTOT, int NTOT, int ROWSH, bool SPLIT_OUT>
__device__ __forceinline__ void gemm_body(
        const __nv_bfloat16* Ahi, const __nv_bfloat16* Alo,
        const __nv_bfloat16* Bhi, const __nv_bfloat16* Blo,
        const float* __restrict__ bias,
        __nv_bfloat16* Ohi, __nv_bfloat16* Olo, float* Ofp) {
    constexpr int NCH = KTOT / BK;
    extern __shared__ __align__(16) char sm[];

    const int e   = blockIdx.z;
    const int cnt = g_cnt[e];
    const int m0  = blockIdx.y * M_T;
    if (m0 >= cnt) return;
    const int n0  = blockIdx.x * N_T;
    const int tid  = threadIdx.x;
    const int wid  = tid >> 5;
    const int lane = tid & 31;
    const int wm = wid & 1;        // 2 warps along M: 64 rows each
    const int wn = wid >> 1;       // 2 warps along N: 64 cols each

    const uint32_t sb = smem_u32(sm);

    // ---- loader setup: 128 threads, 4 segs each for A and for B ------------
    uint32_t dA[4]; size_t ao[4]; int acx[4];
    uint32_t dB[4]; size_t bo[4];
#pragma unroll
    for (int j = 0; j < 4; j++) {
        const int s  = tid + 128 * j;
        const int ar = s >> 2, ac = (s & 3) * 16;       // A: 128 rows x 4 segs
        int am = m0 + ar; if (am >= cnt) am = m0;       // duplicate; discarded
        ao[j]  = (size_t)(g_list[e * NPAIR + am] >> ROWSH) * (KTOT * 2);
        dA[j]  = (uint32_t)(ar * (ALD * 2) + ac);
        acx[j] = ac;
        const int bk = s >> 4, bc = (s & 15) * 16;      // B: 32 rows x 16 segs
        dB[j] = (uint32_t)(bk * (BLD * 2) + bc);
        bo[j] = (((size_t)e * KTOT + bk) * NTOT + n0) * 2 + bc;
    }
    const char* pAh = (const char*)Ahi;
    const char* pAl = (const char*)Alo;
    const char* pBh = (const char*)Bhi;
    const char* pBl = (const char*)Blo;

    auto issue = [&](int c) {
        const uint32_t st = sb + (uint32_t)(c % NSTG) * STG;
        const size_t ga = (size_t)c * (BK * 2);        // A: +64B per chunk
        const size_t gb = (size_t)c * (BK * NTOT * 2); // B: +32 k-rows
#pragma unroll
        for (int j = 0; j < 4; j++) {
            cpa16(st + SA_H + dA[j], pAh + ao[j] + ga + acx[j]);
            cpa16(st + SA_L + dA[j], pAl + ao[j] + ga + acx[j]);
            cpa16(st + SB_H + dB[j], pBh + bo[j] + gb);
            cpa16(st + SB_L + dB[j], pBl + bo[j] + gb);
        }
        cpa_commit();
    };

    wmma::fragment<wmma::accumulator, 16, 16, 16, float> acc[4][4];
#pragma unroll
    for (int mi = 0; mi < 4; mi++)
#pragma unroll
        for (int nj = 0; nj < 4; nj++) wmma::fill_fragment(acc[mi][nj], 0.0f);

    issue(0);
    issue(1);                                  // NCH >= 16 always
    for (int c = 0; c < NCH; c++) {
        if (c + 2 < NCH) { issue(c + 2); cpa_wait<2>(); }
        else if (c + 1 < NCH) { cpa_wait<1>(); }
        else { cpa_wait<0>(); }
        __syncthreads();                       // stage c visible to all warps

        const char* stg = sm + (size_t)(c % NSTG) * STG;
        const __nv_bfloat16* sAh = (const __nv_bfloat16*)(stg + SA_H);
        const __nv_bfloat16* sAl = (const __nv_bfloat16*)(stg + SA_L);
        const __nv_bfloat16* sBh = (const __nv_bfloat16*)(stg + SB_H);
        const __nv_bfloat16* sBl = (const __nv_bfloat16*)(stg + SB_L);
#pragma unroll
        for (int ks = 0; ks < 2; ks++) {
            wmma::fragment<wmma::matrix_a, 16, 16, 16, __nv_bfloat16,
                           wmma::row_major> ah[4], al[4];
#pragma unroll
            for (int mi = 0; mi < 4; mi++) {
                const int ro = (wm * 64 + mi * 16) * ALD + ks * 16;
                wmma::load_matrix_sync(ah[mi], sAh + ro, ALD);
                wmma::load_matrix_sync(al[mi], sAl + ro, ALD);
            }
#pragma unroll
            for (int nj = 0; nj < 4; nj++) {
                wmma::fragment<wmma::matrix_b, 16, 16, 16, __nv_bfloat16,
                               wmma::row_major> bh, bl;
                const int bo2 = (ks * 16) * BLD + wn * 64 + nj * 16;
                wmma::load_matrix_sync(bh, sBh + bo2, BLD);
                wmma::load_matrix_sync(bl, sBl + bo2, BLD);
#pragma unroll
                for (int mi = 0; mi < 4; mi++) {
                    wmma::mma_sync(acc[mi][nj], ah[mi], bh, acc[mi][nj]);
                    wmma::mma_sync(acc[mi][nj], ah[mi], bl, acc[mi][nj]);
                    wmma::mma_sync(acc[mi][nj], al[mi], bh, acc[mi][nj]);
                }
            }
        }
        __syncthreads();                       // stage safe for reuse at c+NSTG
    }

    // ---- epilogue: per-warp 16x16 fp32 staging (pitch 20) ------------------
    float* cs = reinterpret_cast<float*>(sm + wid * (16 * 20 * 4));
    const int r  = lane >> 1;
    const int c0 = (lane & 1) * 8;
#pragma unroll
    for (int mi = 0; mi < 4; mi++) {
#pragma unroll
        for (int nj = 0; nj < 4; nj++) {
            wmma::store_matrix_sync(cs, acc[mi][nj], 20, wmma::mem_row_major);
            __syncwarp();
            const int m = m0 + wm * 64 + mi * 16 + r;
            if (m < cnt) {
                const int pid = g_list[e * NPAIR + m];
                const int nc  = n0 + wn * 64 + nj * 16 + c0;
                const float* bp = bias + (size_t)e * NTOT + nc;
                const float* cp = cs + r * 20 + c0;
                if (SPLIT_OUT) {
                    __nv_bfloat16* oh = Ohi + (size_t)pid * NTOT + nc;
                    __nv_bfloat16* ol = Olo + (size_t)pid * NTOT + nc;
#pragma unroll
                    for (int p = 0; p < 4; p++) {
                        float v0 = cp[2 * p + 0] + bp[2 * p + 0];
                        float v1 = cp[2 * p + 1] + bp[2 * p + 1];
                        __nv_bfloat16 h0 = __float2bfloat16(v0);
                        __nv_bfloat16 h1 = __float2bfloat16(v1);
                        *(__nv_bfloat162*)(oh + 2 * p) = __halves2bfloat162(h0, h1);
                        *(__nv_bfloat162*)(ol + 2 * p) = __halves2bfloat162(
                            __float2bfloat16(v0 - __bfloat162float(h0)),
                            __float2bfloat16(v1 - __bfloat162float(h1)));
                    }
                } else {
                    float* op = Ofp + (size_t)pid * NTOT + nc;
                    float4 w0, w1;
                    w0.x = cp[0] + bp[0]; w0.y = cp[1] + bp[1];
                    w0.z = cp[2] + bp[2]; w0.w = cp[3] + bp[3];
                    w1.x = cp[4] + bp[4]; w1.y = cp[5] + bp[5];
                    w1.z = cp[6] + bp[6]; w1.w = cp[7] + bp[7];
                    *(float4*)(op + 0) = w0;
                    *(float4*)(op + 4) = w1;
                }
            }
            __syncwarp();                       // before cs is overwritten
        }
    }
}

// Concrete wrappers: globals referenced from DEVICE code (correct addresses).
__global__ void __launch_bounds__(128, 2) k_fc1g(const float* __restrict__ b1) {
    gemm_body<DIM, HID, 1, true>(g_xhi, g_xlo, g_w1hi, g_w1lo, b1,
                                 g_Hhi, g_Hlo, nullptr);
}
__global__ void __launch_bounds__(128, 2) k_fc2g(const float* __restrict__ b2) {
    gemm_body<HID, DIM, 0, false>(g_Hhi, g_Hlo, g_w2hi, g_w2lo, b2,
                                  nullptr, nullptr, g_O);
}

// ---------------- combine ----------------------------------------------------
__global__ void k_comb(float* __restrict__ out) {
    int idx = blockIdx.x * blockDim.x + threadIdx.x;
    if (idx >= N_TOK * DIM / 4) return;
    int n  = idx / (DIM / 4);
    int d4 = idx % (DIM / 4);
    float w0 = g_pw[2 * n + 0];
    float w1 = g_pw[2 * n + 1];
    float4 a = *(const float4*)(g_O + (size_t)(2 * n + 0) * DIM + d4 * 4);
    float4 b = *(const float4*)(g_O + (size_t)(2 * n + 1) * DIM + d4 * 4);
    float4 r;
    r.x = w0 * a.x + w1 * b.x;
    r.y = w0 * a.y + w1 * b.y;
    r.z = w0 * a.z + w1 * b.z;
    r.w = w0 * a.w + w1 * b.w;
    *(float4*)(out + (size_t)idx * 4) = r;
}

// ---------------------------------------------------------------------------
extern "C" void kernel_launch(void* const* d_in, const int* in_sizes, int n_in,
                              void* d_out, int out_size) {
    const float* x  = (const float*)d_in[0];
    const float* Wg = (const float*)d_in[1];
    const float* bg = (const float*)d_in[2];
    const float* W1 = (const float*)d_in[3];
    const float* b1 = (const float*)d_in[4];
    const float* W2 = (const float*)d_in[5];
    const float* b2 = (const float*)d_in[6];
    float* out   = (float*)d_out;
    float* usage = out + (size_t)N_TOK * DIM;

    cudaFuncSetAttribute(k_fc1g, cudaFuncAttributeMaxDynamicSharedMemorySize,
                         SMEM_DYN);
    cudaFuncSetAttribute(k_fc2g, cudaFuncAttributeMaxDynamicSharedMemorySize,
                         SMEM_DYN);

    k_zero<<<1, 32>>>(usage);
    k_split_x<<<(N_TOK * DIM / 4 + 255) / 256, 256>>>(x);
    k_split_w<<<(2 * NE * DIM * HID / 4 + 255) / 256, 256>>>(W1, W2);
    k_gate<<<N_TOK / 4, 128>>>(x, Wg, bg, usage);
    k_fc1g<<<dim3(HID / N_T, NPAIR / M_T, NE), 128, SMEM_DYN>>>(b1);
    k_fc2g<<<dim3(DIM / N_T, NPAIR / M_T, NE), 128, SMEM_DYN>>>(b2);
    k_comb<<<(N_TOK * DIM / 4) / 256, 256>>>(out);
}

// round 10
// speedup vs baseline: 2.5659x; 1.0377x over previous
#include <cuda_runtime.h>
#include <cuda_bf16.h>
#include <mma.h>
#include <cstdint>

using namespace nvcuda;

#define N_TOK 4096
#define DIM   512
#define HID   2048
#define NE    8
#define NPAIR (N_TOK * 2)

// GEMM tiling: CTA 128x128, BK=32, 128 threads (4 warps 2x2), warp tile 64x64
#define M_T 128
#define N_T 128
#define BK  32

// smem pitches (elements): A rows 40 (80B), B rows 136 (272B)
#define ALD 40
#define BLD 136
static constexpr int SA_H = 0;               // 128*40*2 = 10240
static constexpr int SA_L = 10240;
static constexpr int SB_H = 20480;           // 32*136*2 = 8704
static constexpr int SB_L = 29184;
static constexpr int STG  = 37888;           // one pipeline stage
static constexpr int NSTG = 3;
static constexpr int SMEM_DYN = NSTG * STG;  // 113664 B -> 2 CTAs/SM

// ---------------- scratch (static device memory; device-code access ONLY) ---
// NOTE: never pass these as kernel arguments from host — host code sees the
// host *shadow* symbol, not the device address (silent corruption via ATS).
__device__ __align__(256) __nv_bfloat16 g_xhi[(size_t)N_TOK * DIM];
__device__ __align__(256) __nv_bfloat16 g_xlo[(size_t)N_TOK * DIM];
__device__ __align__(256) __nv_bfloat16 g_w1hi[(size_t)NE * DIM * HID];
__device__ __align__(256) __nv_bfloat16 g_w1lo[(size_t)NE * DIM * HID];
__device__ __align__(256) __nv_bfloat16 g_w2hi[(size_t)NE * HID * DIM];
__device__ __align__(256) __nv_bfloat16 g_w2lo[(size_t)NE * HID * DIM];
__device__ __align__(256) __nv_bfloat16 g_Hhi[(size_t)NPAIR * HID];
__device__ __align__(256) __nv_bfloat16 g_Hlo[(size_t)NPAIR * HID];
__device__ __align__(256) float g_O[(size_t)NPAIR * DIM];
__device__ __align__(256) float g_pw[NPAIR];
__device__ __align__(256) int   g_list[NE * NPAIR];
__device__ int g_cnt[NE];

// ---------------- PTX helpers ------------------------------------------------
__device__ __forceinline__ uint32_t smem_u32(const void* p) {
    uint32_t a;
    asm("{ .reg .u64 t; cvta.to.shared.u64 t, %1; cvt.u32.u64 %0, t; }"
        : "=r"(a) : "l"(p));
    return a;
}
__device__ __forceinline__ void cpa16(uint32_t s, const void* g) {
    asm volatile("cp.async.cg.shared.global [%0], [%1], 16;"
                 :: "r"(s), "l"(g) : "memory");
}
__device__ __forceinline__ void cpa_commit() {
    asm volatile("cp.async.commit_group;" ::: "memory");
}
template<int N>
__device__ __forceinline__ void cpa_wait() {
    asm volatile("cp.async.wait_group %0;" :: "n"(N) : "memory");
}

// ---------------- aux kernels ------------------------------------------------
__global__ void k_zero(float* __restrict__ usage) {
    int t = threadIdx.x;
    if (t < NE) { g_cnt[t] = 0; usage[t] = 0.0f; }
}

// fp32 -> bf16 hi/lo split of one float4 (index i in float4 units)
__device__ __forceinline__ void split_one(const float* __restrict__ src,
                                          __nv_bfloat16* hi,
                                          __nv_bfloat16* lo, int i) {
    float4 v = ((const float4*)src)[i];
    __nv_bfloat16 h0 = __float2bfloat16(v.x), h1 = __float2bfloat16(v.y);
    __nv_bfloat16 h2 = __float2bfloat16(v.z), h3 = __float2bfloat16(v.w);
    ((__nv_bfloat162*)hi)[i * 2 + 0] = __halves2bfloat162(h0, h1);
    ((__nv_bfloat162*)hi)[i * 2 + 1] = __halves2bfloat162(h2, h3);
    ((__nv_bfloat162*)lo)[i * 2 + 0] = __halves2bfloat162(
        __float2bfloat16(v.x - __bfloat162float(h0)),
        __float2bfloat16(v.y - __bfloat162float(h1)));
    ((__nv_bfloat162*)lo)[i * 2 + 1] = __halves2bfloat162(
        __float2bfloat16(v.z - __bfloat162float(h2)),
        __float2bfloat16(v.w - __bfloat162float(h3)));
}

// fused W1+W2 split: one launch for both weight tensors
__global__ void k_split_w(const float* __restrict__ W1,
                          const float* __restrict__ W2) {
    constexpr int W_N4 = NE * DIM * HID / 4;
    int i = blockIdx.x * blockDim.x + threadIdx.x;
    if (i < W_N4)              split_one(W1, g_w1hi, g_w1lo, i);
    else if (i < 2 * W_N4)     split_one(W2, g_w2hi, g_w2lo, i - W_N4);
}

// ---------------- fused gate + x-split: one pass over x ---------------------
// One warp per token: float4 row loads, hi/lo split write, gating logits from
// smem-transposed Wg ([e][d], padded -> conflict-free float4 LDS).
__global__ void __launch_bounds__(128) k_gatesplit(
        const float* __restrict__ x,
        const float* __restrict__ Wg,
        const float* __restrict__ bg,
        float* __restrict__ usage) {
    __shared__ float wgt[NE][DIM + 4];          // transposed Wg, padded
    const int tid = threadIdx.x;
    for (int i = tid; i < DIM * NE; i += 128) {
        int d = i >> 3, e = i & 7;              // Wg is [d][e]
        wgt[e][d] = Wg[i];
    }
    __syncthreads();

    const int warp = tid >> 5, lane = tid & 31;
    const int n = blockIdx.x * 4 + warp;        // 4 warps per block
    const float4* xr = (const float4*)(x + (size_t)n * DIM);
    __nv_bfloat16* hi = g_xhi + (size_t)n * DIM;
    __nv_bfloat16* lo = g_xlo + (size_t)n * DIM;

    float p[NE];
#pragma unroll
    for (int e = 0; e < NE; e++) p[e] = 0.0f;

#pragma unroll
    for (int j = 0; j < 4; j++) {
        const int d4 = j * 32 + lane;           // float4 index in row (0..127)
        const int d0 = d4 * 4;
        float4 v = xr[d4];
        // split -> bf16 hi/lo (same math/order as before: bit-identical)
        __nv_bfloat16 h0 = __float2bfloat16(v.x), h1 = __float2bfloat16(v.y);
        __nv_bfloat16 h2 = __float2bfloat16(v.z), h3 = __float2bfloat16(v.w);
        ((__nv_bfloat162*)(hi + d0))[0] = __halves2bfloat162(h0, h1);
        ((__nv_bfloat162*)(hi + d0))[1] = __halves2bfloat162(h2, h3);
        ((__nv_bfloat162*)(lo + d0))[0] = __halves2bfloat162(
            __float2bfloat16(v.x - __bfloat162float(h0)),
            __float2bfloat16(v.y - __bfloat162float(h1)));
        ((__nv_bfloat162*)(lo + d0))[1] = __halves2bfloat162(
            __float2bfloat16(v.z - __bfloat162float(h2)),
            __float2bfloat16(v.w - __bfloat162float(h3)));
        // gating logits
#pragma unroll
        for (int e = 0; e < NE; e++) {
            const float4 w = *(const float4*)&wgt[e][d0];
            p[e] = fmaf(v.x, w.x, p[e]);
            p[e] = fmaf(v.y, w.y, p[e]);
            p[e] = fmaf(v.z, w.z, p[e]);
            p[e] = fmaf(v.w, w.w, p[e]);
        }
    }
#pragma unroll
    for (int o = 16; o; o >>= 1)
#pragma unroll
        for (int e = 0; e < NE; e++) p[e] += __shfl_xor_sync(0xffffffffu, p[e], o);

    if (lane == 0) {
#pragma unroll
        for (int e = 0; e < NE; e++) p[e] += bg[e];
        int i0 = 0;
#pragma unroll
        for (int e = 1; e < NE; e++) if (p[e] > p[i0]) i0 = e;
        int i1 = (i0 == 0) ? 1 : 0;
#pragma unroll
        for (int e = 0; e < NE; e++) if (e != i0 && p[e] > p[i1]) i1 = e;
        float w0 = 1.0f / (1.0f + expf(p[i1] - p[i0]));
        float w1 = 1.0f - w0;
        g_pw[2 * n + 0] = w0;
        g_pw[2 * n + 1] = w1;
        atomicAdd(&usage[i0], w0);
        atomicAdd(&usage[i1], w1);
        int q0 = atomicAdd(&g_cnt[i0], 1); g_list[i0 * NPAIR + q0] = 2 * n;
        int q1 = atomicAdd(&g_cnt[i1], 1); g_list[i1 * NPAIR + q1] = 2 * n + 1;
    }
}

// ---------------- grouped GEMM via wmma + 3-stage cp.async pipeline ---------
// D[m,n] = sum_k A[m,k] * B[k,n] + bias[n]
// A: gathered rows via g_list (row = pid>>ROWSH), K-major [*, KTOT]
// B: [E][KTOT][NTOT] row-major.  SPLIT_OUT: emit hi/lo bf16 (fc1) else fp32.
// 128 threads, 4 warps (2x2), warp tile 64x64.
template<int KTOT, int NTOT, int ROWSH, bool SPLIT_OUT>
__device__ __forceinline__ void gemm_body(
        const __nv_bfloat16* Ahi, const __nv_bfloat16* Alo,
        const __nv_bfloat16* Bhi, const __nv_bfloat16* Blo,
        const float* __restrict__ bias,
        __nv_bfloat16* Ohi, __nv_bfloat16* Olo, float* Ofp) {
    constexpr int NCH = KTOT / BK;
    extern __shared__ __align__(16) char sm[];

    const int e   = blockIdx.z;
    const int cnt = g_cnt[e];
    const int m0  = blockIdx.y * M_T;
    if (m0 >= cnt) return;
    const int n0  = blockIdx.x * N_T;
    const int tid  = threadIdx.x;
    const int wid  = tid >> 5;
    const int lane = tid & 31;
    const int wm = wid & 1;        // 2 warps along M: 64 rows each
    const int wn = wid >> 1;       // 2 warps along N: 64 cols each

    const uint32_t sb = smem_u32(sm);

    // ---- loader setup: 128 threads, 4 segs each for A and for B ------------
    uint32_t dA[4]; size_t ao[4]; int acx[4];
    uint32_t dB[4]; size_t bo[4];
#pragma unroll
    for (int j = 0; j < 4; j++) {
        const int s  = tid + 128 * j;
        const int ar = s >> 2, ac = (s & 3) * 16;       // A: 128 rows x 4 segs
        int am = m0 + ar; if (am >= cnt) am = m0;       // duplicate; discarded
        ao[j]  = (size_t)(g_list[e * NPAIR + am] >> ROWSH) * (KTOT * 2);
        dA[j]  = (uint32_t)(ar * (ALD * 2) + ac);
        acx[j] = ac;
        const int bk = s >> 4, bc = (s & 15) * 16;      // B: 32 rows x 16 segs
        dB[j] = (uint32_t)(bk * (BLD * 2) + bc);
        bo[j] = (((size_t)e * KTOT + bk) * NTOT + n0) * 2 + bc;
    }
    const char* pAh = (const char*)Ahi;
    const char* pAl = (const char*)Alo;
    const char* pBh = (const char*)Bhi;
    const char* pBl = (const char*)Blo;

    auto issue = [&](int c) {
        const uint32_t st = sb + (uint32_t)(c % NSTG) * STG;
        const size_t ga = (size_t)c * (BK * 2);        // A: +64B per chunk
        const size_t gb = (size_t)c * (BK * NTOT * 2); // B: +32 k-rows
#pragma unroll
        for (int j = 0; j < 4; j++) {
            cpa16(st + SA_H + dA[j], pAh + ao[j] + ga + acx[j]);
            cpa16(st + SA_L + dA[j], pAl + ao[j] + ga + acx[j]);
            cpa16(st + SB_H + dB[j], pBh + bo[j] + gb);
            cpa16(st + SB_L + dB[j], pBl + bo[j] + gb);
        }
        cpa_commit();
    };

    wmma::fragment<wmma::accumulator, 16, 16, 16, float> acc[4][4];
#pragma unroll
    for (int mi = 0; mi < 4; mi++)
#pragma unroll
        for (int nj = 0; nj < 4; nj++) wmma::fill_fragment(acc[mi][nj], 0.0f);

    issue(0);
    issue(1);                                  // NCH >= 16 always
    for (int c = 0; c < NCH; c++) {
        if (c + 2 < NCH) { issue(c + 2); cpa_wait<2>(); }
        else if (c + 1 < NCH) { cpa_wait<1>(); }
        else { cpa_wait<0>(); }
        __syncthreads();                       // stage c visible to all warps

        const char* stg = sm + (size_t)(c % NSTG) * STG;
        const __nv_bfloat16* sAh = (const __nv_bfloat16*)(stg + SA_H);
        const __nv_bfloat16* sAl = (const __nv_bfloat16*)(stg + SA_L);
        const __nv_bfloat16* sBh = (const __nv_bfloat16*)(stg + SB_H);
        const __nv_bfloat16* sBl = (const __nv_bfloat16*)(stg + SB_L);
#pragma unroll
        for (int ks = 0; ks < 2; ks++) {
            wmma::fragment<wmma::matrix_a, 16, 16, 16, __nv_bfloat16,
                           wmma::row_major> ah[4], al[4];
#pragma unroll
            for (int mi = 0; mi < 4; mi++) {
                const int ro = (wm * 64 + mi * 16) * ALD + ks * 16;
                wmma::load_matrix_sync(ah[mi], sAh + ro, ALD);
                wmma::load_matrix_sync(al[mi], sAl + ro, ALD);
            }
#pragma unroll
            for (int nj = 0; nj < 4; nj++) {
                wmma::fragment<wmma::matrix_b, 16, 16, 16, __nv_bfloat16,
                               wmma::row_major> bh, bl;
                const int bo2 = (ks * 16) * BLD + wn * 64 + nj * 16;
                wmma::load_matrix_sync(bh, sBh + bo2, BLD);
                wmma::load_matrix_sync(bl, sBl + bo2, BLD);
#pragma unroll
                for (int mi = 0; mi < 4; mi++) {
                    wmma::mma_sync(acc[mi][nj], ah[mi], bh, acc[mi][nj]);
                    wmma::mma_sync(acc[mi][nj], ah[mi], bl, acc[mi][nj]);
                    wmma::mma_sync(acc[mi][nj], al[mi], bh, acc[mi][nj]);
                }
            }
        }
        __syncthreads();                       // stage safe for reuse at c+NSTG
    }

    // ---- epilogue: per-warp 16x16 fp32 staging (pitch 20) ------------------
    float* cs = reinterpret_cast<float*>(sm + wid * (16 * 20 * 4));
    const int r  = lane >> 1;
    const int c0 = (lane & 1) * 8;
#pragma unroll
    for (int mi = 0; mi < 4; mi++) {
#pragma unroll
        for (int nj = 0; nj < 4; nj++) {
            wmma::store_matrix_sync(cs, acc[mi][nj], 20, wmma::mem_row_major);
            __syncwarp();
            const int m = m0 + wm * 64 + mi * 16 + r;
            if (m < cnt) {
                const int pid = g_list[e * NPAIR + m];
                const int nc  = n0 + wn * 64 + nj * 16 + c0;
                const float* bp = bias + (size_t)e * NTOT + nc;
                const float* cp = cs + r * 20 + c0;
                if (SPLIT_OUT) {
                    __nv_bfloat16* oh = Ohi + (size_t)pid * NTOT + nc;
                    __nv_bfloat16* ol = Olo + (size_t)pid * NTOT + nc;
#pragma unroll
                    for (int p = 0; p < 4; p++) {
                        float v0 = cp[2 * p + 0] + bp[2 * p + 0];
                        float v1 = cp[2 * p + 1] + bp[2 * p + 1];
                        __nv_bfloat16 h0 = __float2bfloat16(v0);
                        __nv_bfloat16 h1 = __float2bfloat16(v1);
                        *(__nv_bfloat162*)(oh + 2 * p) = __halves2bfloat162(h0, h1);
                        *(__nv_bfloat162*)(ol + 2 * p) = __halves2bfloat162(
                            __float2bfloat16(v0 - __bfloat162float(h0)),
                            __float2bfloat16(v1 - __bfloat162float(h1)));
                    }
                } else {
                    float* op = Ofp + (size_t)pid * NTOT + nc;
                    float4 w0, w1;
                    w0.x = cp[0] + bp[0]; w0.y = cp[1] + bp[1];
                    w0.z = cp[2] + bp[2]; w0.w = cp[3] + bp[3];
                    w1.x = cp[4] + bp[4]; w1.y = cp[5] + bp[5];
                    w1.z = cp[6] + bp[6]; w1.w = cp[7] + bp[7];
                    *(float4*)(op + 0) = w0;
                    *(float4*)(op + 4) = w1;
                }
            }
            __syncwarp();                       // before cs is overwritten
        }
    }
}

// Concrete wrappers: globals referenced from DEVICE code (correct addresses).
__global__ void __launch_bounds__(128, 2) k_fc1g(const float* __restrict__ b1) {
    gemm_body<DIM, HID, 1, true>(g_xhi, g_xlo, g_w1hi, g_w1lo, b1,
                                 g_Hhi, g_Hlo, nullptr);
}
__global__ void __launch_bounds__(128, 2) k_fc2g(const float* __restrict__ b2) {
    gemm_body<HID, DIM, 0, false>(g_Hhi, g_Hlo, g_w2hi, g_w2lo, b2,
                                  nullptr, nullptr, g_O);
}

// ---------------- combine ----------------------------------------------------
__global__ void k_comb(float* __restrict__ out) {
    int idx = blockIdx.x * blockDim.x + threadIdx.x;
    if (idx >= N_TOK * DIM / 4) return;
    int n  = idx / (DIM / 4);
    int d4 = idx % (DIM / 4);
    float w0 = g_pw[2 * n + 0];
    float w1 = g_pw[2 * n + 1];
    float4 a = *(const float4*)(g_O + (size_t)(2 * n + 0) * DIM + d4 * 4);
    float4 b = *(const float4*)(g_O + (size_t)(2 * n + 1) * DIM + d4 * 4);
    float4 r;
    r.x = w0 * a.x + w1 * b.x;
    r.y = w0 * a.y + w1 * b.y;
    r.z = w0 * a.z + w1 * b.z;
    r.w = w0 * a.w + w1 * b.w;
    *(float4*)(out + (size_t)idx * 4) = r;
}

// ---------------------------------------------------------------------------
extern "C" void kernel_launch(void* const* d_in, const int* in_sizes, int n_in,
                              void* d_out, int out_size) {
    const float* x  = (const float*)d_in[0];
    const float* Wg = (const float*)d_in[1];
    const float* bg = (const float*)d_in[2];
    const float* W1 = (const float*)d_in[3];
    const float* b1 = (const float*)d_in[4];
    const float* W2 = (const float*)d_in[5];
    const float* b2 = (const float*)d_in[6];
    float* out   = (float*)d_out;
    float* usage = out + (size_t)N_TOK * DIM;

    cudaFuncSetAttribute(k_fc1g, cudaFuncAttributeMaxDynamicSharedMemorySize,
                         SMEM_DYN);
    cudaFuncSetAttribute(k_fc2g, cudaFuncAttributeMaxDynamicSharedMemorySize,
                         SMEM_DYN);

    k_zero<<<1, 32>>>(usage);
    k_split_w<<<(2 * NE * DIM * HID / 4 + 255) / 256, 256>>>(W1, W2);
    k_gatesplit<<<N_TOK / 4, 128>>>(x, Wg, bg, usage);
    k_fc1g<<<dim3(HID / N_T, NPAIR / M_T, NE), 128, SMEM_DYN>>>(b1);
    k_fc2g<<<dim3(DIM / N_T, NPAIR / M_T, NE), 128, SMEM_DYN>>>(b2);
    k_comb<<<(N_TOK * DIM / 4) / 256, 256>>>(out);
}

// round 12
// speedup vs baseline: 2.5679x; 1.0008x over previous
#include <cuda_runtime.h>
#include <cuda_bf16.h>
#include <mma.h>
#include <cstdint>

using namespace nvcuda;

#define N_TOK 4096
#define DIM   512
#define HID   2048
#define NE    8
#define NPAIR (N_TOK * 2)

// GEMM tiling: CTA 128x128, BK=32, 128 threads (4 warps 2x2), warp tile 64x64
#define M_T 128
#define N_T 128
#define BK  32

// smem pitches (elements): A rows 40 (80B), B rows 136 (272B)
#define ALD 40
#define BLD 136
static constexpr int SA_H = 0;               // 128*40*2 = 10240
static constexpr int SA_L = 10240;
static constexpr int SB_H = 20480;           // 32*136*2 = 8704
static constexpr int SB_L = 29184;
static constexpr int STG  = 37888;           // one pipeline stage
static constexpr int NSTG = 3;
static constexpr int SMEM_DYN = NSTG * STG;  // 113664 B -> 2 CTAs/SM

// ---------------- scratch (static device memory; device-code access ONLY) ---
// NOTE: never pass these as kernel arguments from host — host code sees the
// host *shadow* symbol, not the device address (silent corruption via ATS).
__device__ __align__(256) __nv_bfloat16 g_xhi[(size_t)N_TOK * DIM];
__device__ __align__(256) __nv_bfloat16 g_xlo[(size_t)N_TOK * DIM];
__device__ __align__(256) __nv_bfloat16 g_w1hi[(size_t)NE * DIM * HID];
__device__ __align__(256) __nv_bfloat16 g_w1lo[(size_t)NE * DIM * HID];
__device__ __align__(256) __nv_bfloat16 g_w2hi[(size_t)NE * HID * DIM];
__device__ __align__(256) __nv_bfloat16 g_w2lo[(size_t)NE * HID * DIM];
__device__ __align__(256) __nv_bfloat16 g_Hhi[(size_t)NPAIR * HID];
__device__ __align__(256) __nv_bfloat16 g_Hlo[(size_t)NPAIR * HID];
__device__ __align__(256) float g_O[(size_t)NPAIR * DIM];
__device__ __align__(256) float g_pw[NPAIR];
__device__ __align__(256) int   g_list[NE * NPAIR];
__device__ int g_cnt[NE];

// ---------------- PTX helpers ------------------------------------------------
__device__ __forceinline__ uint32_t smem_u32(const void* p) {
    uint32_t a;
    asm("{ .reg .u64 t; cvta.to.shared.u64 t, %1; cvt.u32.u64 %0, t; }"
        : "=r"(a) : "l"(p));
    return a;
}
__device__ __forceinline__ void cpa16(uint32_t s, const void* g) {
    asm volatile("cp.async.cg.shared.global [%0], [%1], 16;"
                 :: "r"(s), "l"(g) : "memory");
}
__device__ __forceinline__ void cpa_commit() {
    asm volatile("cp.async.commit_group;" ::: "memory");
}
template<int N>
__device__ __forceinline__ void cpa_wait() {
    asm volatile("cp.async.wait_group %0;" :: "n"(N) : "memory");
}

// ---------------- aux kernels ------------------------------------------------
__global__ void k_zero(float* __restrict__ usage) {
    int t = threadIdx.x;
    if (t < NE) { g_cnt[t] = 0; usage[t] = 0.0f; }
}

// fp32 -> bf16 hi/lo split of one float4 (index i in float4 units)
__device__ __forceinline__ void split_one(const float* __restrict__ src,
                                          __nv_bfloat16* hi,
                                          __nv_bfloat16* lo, int i) {
    float4 v = ((const float4*)src)[i];
    __nv_bfloat16 h0 = __float2bfloat16(v.x), h1 = __float2bfloat16(v.y);
    __nv_bfloat16 h2 = __float2bfloat16(v.z), h3 = __float2bfloat16(v.w);
    ((__nv_bfloat162*)hi)[i * 2 + 0] = __halves2bfloat162(h0, h1);
    ((__nv_bfloat162*)hi)[i * 2 + 1] = __halves2bfloat162(h2, h3);
    ((__nv_bfloat162*)lo)[i * 2 + 0] = __halves2bfloat162(
        __float2bfloat16(v.x - __bfloat162float(h0)),
        __float2bfloat16(v.y - __bfloat162float(h1)));
    ((__nv_bfloat162*)lo)[i * 2 + 1] = __halves2bfloat162(
        __float2bfloat16(v.z - __bfloat162float(h2)),
        __float2bfloat16(v.w - __bfloat162float(h3)));
}

// fused W1+W2 split: one launch for both weight tensors
__global__ void k_split_w(const float* __restrict__ W1,
                          const float* __restrict__ W2) {
    constexpr int W_N4 = NE * DIM * HID / 4;
    int i = blockIdx.x * blockDim.x + threadIdx.x;
    if (i < W_N4)              split_one(W1, g_w1hi, g_w1lo, i);
    else if (i < 2 * W_N4)     split_one(W2, g_w2hi, g_w2lo, i - W_N4);
}

// ---------------- fused gate + x-split: one pass over x ---------------------
__global__ void __launch_bounds__(128) k_gatesplit(
        const float* __restrict__ x,
        const float* __restrict__ Wg,
        const float* __restrict__ bg,
        float* __restrict__ usage) {
    __shared__ float wgt[NE][DIM + 4];          // transposed Wg, padded
    const int tid = threadIdx.x;
    for (int i = tid; i < DIM * NE; i += 128) {
        int d = i >> 3, e = i & 7;              // Wg is [d][e]
        wgt[e][d] = Wg[i];
    }
    __syncthreads();

    const int warp = tid >> 5, lane = tid & 31;
    const int n = blockIdx.x * 4 + warp;        // 4 warps per block
    const float4* xr = (const float4*)(x + (size_t)n * DIM);
    __nv_bfloat16* hi = g_xhi + (size_t)n * DIM;
    __nv_bfloat16* lo = g_xlo + (size_t)n * DIM;

    float p[NE];
#pragma unroll
    for (int e = 0; e < NE; e++) p[e] = 0.0f;

#pragma unroll
    for (int j = 0; j < 4; j++) {
        const int d4 = j * 32 + lane;           // float4 index in row (0..127)
        const int d0 = d4 * 4;
        float4 v = xr[d4];
        __nv_bfloat16 h0 = __float2bfloat16(v.x), h1 = __float2bfloat16(v.y);
        __nv_bfloat16 h2 = __float2bfloat16(v.z), h3 = __float2bfloat16(v.w);
        ((__nv_bfloat162*)(hi + d0))[0] = __halves2bfloat162(h0, h1);
        ((__nv_bfloat162*)(hi + d0))[1] = __halves2bfloat162(h2, h3);
        ((__nv_bfloat162*)(lo + d0))[0] = __halves2bfloat162(
            __float2bfloat16(v.x - __bfloat162float(h0)),
            __float2bfloat16(v.y - __bfloat162float(h1)));
        ((__nv_bfloat162*)(lo + d0))[1] = __halves2bfloat162(
            __float2bfloat16(v.z - __bfloat162float(h2)),
            __float2bfloat16(v.w - __bfloat162float(h3)));
#pragma unroll
        for (int e = 0; e < NE; e++) {
            const float4 w = *(const float4*)&wgt[e][d0];
            p[e] = fmaf(v.x, w.x, p[e]);
            p[e] = fmaf(v.y, w.y, p[e]);
            p[e] = fmaf(v.z, w.z, p[e]);
            p[e] = fmaf(v.w, w.w, p[e]);
        }
    }
#pragma unroll
    for (int o = 16; o; o >>= 1)
#pragma unroll
        for (int e = 0; e < NE; e++) p[e] += __shfl_xor_sync(0xffffffffu, p[e], o);

    if (lane == 0) {
#pragma unroll
        for (int e = 0; e < NE; e++) p[e] += bg[e];
        int i0 = 0;
#pragma unroll
        for (int e = 1; e < NE; e++) if (p[e] > p[i0]) i0 = e;
        int i1 = (i0 == 0) ? 1 : 0;
#pragma unroll
        for (int e = 0; e < NE; e++) if (e != i0 && p[e] > p[i1]) i1 = e;
        float w0 = 1.0f / (1.0f + expf(p[i1] - p[i0]));
        float w1 = 1.0f - w0;
        g_pw[2 * n + 0] = w0;
        g_pw[2 * n + 1] = w1;
        atomicAdd(&usage[i0], w0);
        atomicAdd(&usage[i1], w1);
        int q0 = atomicAdd(&g_cnt[i0], 1); g_list[i0 * NPAIR + q0] = 2 * n;
        int q1 = atomicAdd(&g_cnt[i1], 1); g_list[i1 * NPAIR + q1] = 2 * n + 1;
    }
}

// ---------------- grouped GEMM via wmma + 3-stage cp.async pipeline ---------
// Single __syncthreads per chunk: wait(c) -> sync -> compute(c) -> issue(c+2).
// issue(c+2) writes stage (c-1)%3: safe, all warps passed sync after compute(c-1).
// 32-bit global offsets (all scratch < 4GB) to relieve register pressure.
template<int KTOT, int NTOT, int ROWSH, bool SPLIT_OUT>
__device__ __forceinline__ void gemm_body(
        const __nv_bfloat16* Ahi, const __nv_bfloat16* Alo,
        const __nv_bfloat16* Bhi, const __nv_bfloat16* Blo,
        const float* __restrict__ bias,
        __nv_bfloat16* Ohi, __nv_bfloat16* Olo, float* Ofp) {
    constexpr int NCH = KTOT / BK;
    extern __shared__ __align__(16) char sm[];

    const int e   = blockIdx.z;
    const int cnt = g_cnt[e];
    const int m0  = blockIdx.y * M_T;
    if (m0 >= cnt) return;
    const int n0  = blockIdx.x * N_T;
    const int tid  = threadIdx.x;
    const int wid  = tid >> 5;
    const int lane = tid & 31;
    const int wm = wid & 1;        // 2 warps along M: 64 rows each
    const int wn = wid >> 1;       // 2 warps along N: 64 cols each

    const uint32_t sb = smem_u32(sm);

    // ---- loader setup: 128 threads, 4 segs each for A and for B ------------
    uint32_t dA[4], aoff[4];       // aoff includes the column-16 byte offset
    uint32_t dB[4], boff[4];
#pragma unroll
    for (int j = 0; j < 4; j++) {
        const int s  = tid + 128 * j;
        const int ar = s >> 2, ac = (s & 3) * 16;       // A: 128 rows x 4 segs
        int am = m0 + ar; if (am >= cnt) am = m0;       // duplicate; discarded
        aoff[j] = (uint32_t)((g_list[e * NPAIR + am] >> ROWSH) * (KTOT * 2)) + ac;
        dA[j]   = (uint32_t)(ar * (ALD * 2) + ac);
        const int bk = s >> 4, bc = (s & 15) * 16;      // B: 32 rows x 16 segs
        dB[j]   = (uint32_t)(bk * (BLD * 2) + bc);
        boff[j] = (uint32_t)(((e * KTOT + bk) * NTOT + n0) * 2 + bc);
    }
    const char* pAh = (const char*)Ahi;
    const char* pAl = (const char*)Alo;
    const char* pBh = (const char*)Bhi;
    const char* pBl = (const char*)Blo;

    auto issue = [&](int c) {
        const uint32_t st = sb + (uint32_t)(c % NSTG) * STG;
        const uint32_t ga = (uint32_t)c * (BK * 2);        // A: +64B per chunk
        const uint32_t gb = (uint32_t)c * (BK * NTOT * 2); // B: +32 k-rows
#pragma unroll
        for (int j = 0; j < 4; j++) {
            cpa16(st + SA_H + dA[j], pAh + aoff[j] + ga);
            cpa16(st + SA_L + dA[j], pAl + aoff[j] + ga);
            cpa16(st + SB_H + dB[j], pBh + boff[j] + gb);
            cpa16(st + SB_L + dB[j], pBl + boff[j] + gb);
        }
        cpa_commit();
    };

    wmma::fragment<wmma::accumulator, 16, 16, 16, float> acc[4][4];
#pragma unroll
    for (int mi = 0; mi < 4; mi++)
#pragma unroll
        for (int nj = 0; nj < 4; nj++) wmma::fill_fragment(acc[mi][nj], 0.0f);

    issue(0);
    issue(1);                                  // NCH >= 16 always
    for (int c = 0; c < NCH; c++) {
        if (c + 1 < NCH) cpa_wait<1>();        // stage c arrived
        else             cpa_wait<0>();
        __syncthreads();                       // ...and visible to all warps

        const char* stg = sm + (size_t)(c % NSTG) * STG;
        const __nv_bfloat16* sAh = (const __nv_bfloat16*)(stg + SA_H);
        const __nv_bfloat16* sAl = (const __nv_bfloat16*)(stg + SA_L);
        const __nv_bfloat16* sBh = (const __nv_bfloat16*)(stg + SB_H);
        const __nv_bfloat16* sBl = (const __nv_bfloat16*)(stg + SB_L);
#pragma unroll
        for (int ks = 0; ks < 2; ks++) {
            wmma::fragment<wmma::matrix_a, 16, 16, 16, __nv_bfloat16,
                           wmma::row_major> ah[4], al[4];
#pragma unroll
            for (int mi = 0; mi < 4; mi++) {
                const int ro = (wm * 64 + mi * 16) * ALD + ks * 16;
                wmma::load_matrix_sync(ah[mi], sAh + ro, ALD);
                wmma::load_matrix_sync(al[mi], sAl + ro, ALD);
            }
#pragma unroll
            for (int nj = 0; nj < 4; nj++) {
                wmma::fragment<wmma::matrix_b, 16, 16, 16, __nv_bfloat16,
                               wmma::row_major> bh, bl;
                const int bo2 = (ks * 16) * BLD + wn * 64 + nj * 16;
                wmma::load_matrix_sync(bh, sBh + bo2, BLD);
                wmma::load_matrix_sync(bl, sBl + bo2, BLD);
#pragma unroll
                for (int mi = 0; mi < 4; mi++) {
                    wmma::mma_sync(acc[mi][nj], ah[mi], bh, acc[mi][nj]);
                    wmma::mma_sync(acc[mi][nj], ah[mi], bl, acc[mi][nj]);
                    wmma::mma_sync(acc[mi][nj], al[mi], bh, acc[mi][nj]);
                }
            }
        }
        if (c + 2 < NCH) issue(c + 2);         // into stage (c-1)%3: safe
    }
    __syncthreads();                            // done with tiles; reuse as cs

    // ---- epilogue: per-warp 16x16 fp32 staging (pitch 20) ------------------
    float* cs = reinterpret_cast<float*>(sm + wid * (16 * 20 * 4));
    const int r  = lane >> 1;
    const int c0 = (lane & 1) * 8;
#pragma unroll
    for (int mi = 0; mi < 4; mi++) {
#pragma unroll
        for (int nj = 0; nj < 4; nj++) {
            wmma::store_matrix_sync(cs, acc[mi][nj], 20, wmma::mem_row_major);
            __syncwarp();
            const int m = m0 + wm * 64 + mi * 16 + r;
            if (m < cnt) {
                const int pid = g_list[e * NPAIR + m];
                const int nc  = n0 + wn * 64 + nj * 16 + c0;
                const float* bp = bias + (size_t)e * NTOT + nc;
                const float* cp = cs + r * 20 + c0;
                if (SPLIT_OUT) {
                    __nv_bfloat16* oh = Ohi + (size_t)pid * NTOT + nc;
                    __nv_bfloat16* ol = Olo + (size_t)pid * NTOT + nc;
#pragma unroll
                    for (int p = 0; p < 4; p++) {
                        float v0 = cp[2 * p + 0] + bp[2 * p + 0];
                        float v1 = cp[2 * p + 1] + bp[2 * p + 1];
                        __nv_bfloat16 h0 = __float2bfloat16(v0);
                        __nv_bfloat16 h1 = __float2bfloat16(v1);
                        *(__nv_bfloat162*)(oh + 2 * p) = __halves2bfloat162(h0, h1);
                        *(__nv_bfloat162*)(ol + 2 * p) = __halves2bfloat162(
                            __float2bfloat16(v0 - __bfloat162float(h0)),
                            __float2bfloat16(v1 - __bfloat162float(h1)));
                    }
                } else {
                    float* op = Ofp + (size_t)pid * NTOT + nc;
                    float4 w0, w1;
                    w0.x = cp[0] + bp[0]; w0.y = cp[1] + bp[1];
                    w0.z = cp[2] + bp[2]; w0.w = cp[3] + bp[3];
                    w1.x = cp[4] + bp[4]; w1.y = cp[5] + bp[5];
                    w1.z = cp[6] + bp[6]; w1.w = cp[7] + bp[7];
                    *(float4*)(op + 0) = w0;
                    *(float4*)(op + 4) = w1;
                }
            }
            __syncwarp();                       // before cs is overwritten
        }
    }
}

// Concrete wrappers: globals referenced from DEVICE code (correct addresses).
__global__ void __launch_bounds__(128, 2) k_fc1g(const float* __restrict__ b1) {
    gemm_body<DIM, HID, 1, true>(g_xhi, g_xlo, g_w1hi, g_w1lo, b1,
                                 g_Hhi, g_Hlo, nullptr);
}
__global__ void __launch_bounds__(128, 2) k_fc2g(const float* __restrict__ b2) {
    gemm_body<HID, DIM, 0, false>(g_Hhi, g_Hlo, g_w2hi, g_w2lo, b2,
                                  nullptr, nullptr, g_O);
}

// ---------------- combine ----------------------------------------------------
__global__ void k_comb(float* __restrict__ out) {
    int idx = blockIdx.x * blockDim.x + threadIdx.x;
    if (idx >= N_TOK * DIM / 4) return;
    int n  = idx / (DIM / 4);
    int d4 = idx % (DIM / 4);
    float w0 = g_pw[2 * n + 0];
    float w1 = g_pw[2 * n + 1];
    float4 a = *(const float4*)(g_O + (size_t)(2 * n + 0) * DIM + d4 * 4);
    float4 b = *(const float4*)(g_O + (size_t)(2 * n + 1) * DIM + d4 * 4);
    float4 r;
    r.x = w0 * a.x + w1 * b.x;
    r.y = w0 * a.y + w1 * b.y;
    r.z = w0 * a.z + w1 * b.z;
    r.w = w0 * a.w + w1 * b.w;
    *(float4*)(out + (size_t)idx * 4) = r;
}

// ---------------------------------------------------------------------------
extern "C" void kernel_launch(void* const* d_in, const int* in_sizes, int n_in,
                              void* d_out, int out_size) {
    const float* x  = (const float*)d_in[0];
    const float* Wg = (const float*)d_in[1];
    const float* bg = (const float*)d_in[2];
    const float* W1 = (const float*)d_in[3];
    const float* b1 = (const float*)d_in[4];
    const float* W2 = (const float*)d_in[5];
    const float* b2 = (const float*)d_in[6];
    float* out   = (float*)d_out;
    float* usage = out + (size_t)N_TOK * DIM;

    cudaFuncSetAttribute(k_fc1g, cudaFuncAttributeMaxDynamicSharedMemorySize,
                         SMEM_DYN);
    cudaFuncSetAttribute(k_fc2g, cudaFuncAttributeMaxDynamicSharedMemorySize,
                         SMEM_DYN);

    k_zero<<<1, 32>>>(usage);
    k_split_w<<<(2 * NE * DIM * HID / 4 + 255) / 256, 256>>>(W1, W2);
    k_gatesplit<<<N_TOK / 4, 128>>>(x, Wg, bg, usage);
    k_fc1g<<<dim3(HID / N_T, NPAIR / M_T, NE), 128, SMEM_DYN>>>(b1);
    k_fc2g<<<dim3(DIM / N_T, NPAIR / M_T, NE), 128, SMEM_DYN>>>(b2);
    k_comb<<<(N_TOK * DIM / 4) / 256, 256>>>(out);
}

// round 13
// speedup vs baseline: 6.0971x; 2.3743x over previous
#include <cuda_runtime.h>
#include <cuda_fp16.h>
#include <mma.h>
#include <cstdint>

using namespace nvcuda;

#define N_TOK 4096
#define DIM   512
#define HID   2048
#define NE    8
#define NPAIR (N_TOK * 2)

// GEMM tiling: CTA 128x128, BK=32, 128 threads (4 warps 2x2), warp tile 64x64
#define M_T 128
#define N_T 128
#define BK  32

// smem pitches (elements): A rows 40 (80B), B rows 136 (272B)
#define ALD 40
#define BLD 136
static constexpr int SA = 0;                 // 128*40*2 = 10240
static constexpr int SB = 10240;             // 32*136*2 = 8704
static constexpr int STG  = 18944;           // one pipeline stage
static constexpr int NSTG = 3;
static constexpr int SMEM_DYN = NSTG * STG;  // 56832 B -> 2 CTAs/SM easily

// ---------------- scratch (static device memory; device-code access ONLY) ---
// NOTE: never pass these as kernel arguments from host — host code sees the
// host *shadow* symbol, not the device address (silent corruption via ATS).
__device__ __align__(256) __half g_xh[(size_t)N_TOK * DIM];
__device__ __align__(256) __half g_w1h[(size_t)NE * DIM * HID];
__device__ __align__(256) __half g_w2h[(size_t)NE * HID * DIM];
__device__ __align__(256) __half g_Hh[(size_t)NPAIR * HID];
__device__ __align__(256) float g_O[(size_t)NPAIR * DIM];
__device__ __align__(256) float g_pw[NPAIR];
__device__ __align__(256) int   g_list[NE * NPAIR];
__device__ int g_cnt[NE];

// ---------------- PTX helpers ------------------------------------------------
__device__ __forceinline__ uint32_t smem_u32(const void* p) {
    uint32_t a;
    asm("{ .reg .u64 t; cvta.to.shared.u64 t, %1; cvt.u32.u64 %0, t; }"
        : "=r"(a) : "l"(p));
    return a;
}
__device__ __forceinline__ void cpa16(uint32_t s, const void* g) {
    asm volatile("cp.async.cg.shared.global [%0], [%1], 16;"
                 :: "r"(s), "l"(g) : "memory");
}
__device__ __forceinline__ void cpa_commit() {
    asm volatile("cp.async.commit_group;" ::: "memory");
}
template<int N>
__device__ __forceinline__ void cpa_wait() {
    asm volatile("cp.async.wait_group %0;" :: "n"(N) : "memory");
}

// ---------------- aux kernels ------------------------------------------------
__global__ void k_zero(float* __restrict__ usage) {
    int t = threadIdx.x;
    if (t < NE) { g_cnt[t] = 0; usage[t] = 0.0f; }
}

// fused W1+W2 convert: fp32 -> fp16, one launch for both weight tensors
__global__ void k_split_w(const float* __restrict__ W1,
                          const float* __restrict__ W2) {
    constexpr int W_N4 = NE * DIM * HID / 4;
    int i = blockIdx.x * blockDim.x + threadIdx.x;
    const float* src; __half* dst; int j;
    if (i < W_N4)          { src = W1; dst = g_w1h; j = i; }
    else if (i < 2 * W_N4) { src = W2; dst = g_w2h; j = i - W_N4; }
    else return;
    float4 v = ((const float4*)src)[j];
    ((half2*)dst)[j * 2 + 0] = __floats2half2_rn(v.x, v.y);
    ((half2*)dst)[j * 2 + 1] = __floats2half2_rn(v.z, v.w);
}

// ---------------- fused gate + x-convert: one pass over x -------------------
__global__ void __launch_bounds__(128) k_gatesplit(
        const float* __restrict__ x,
        const float* __restrict__ Wg,
        const float* __restrict__ bg,
        float* __restrict__ usage) {
    __shared__ float wgt[NE][DIM + 4];          // transposed Wg, padded
    const int tid = threadIdx.x;
    for (int i = tid; i < DIM * NE; i += 128) {
        int d = i >> 3, e = i & 7;              // Wg is [d][e]
        wgt[e][d] = Wg[i];
    }
    __syncthreads();

    const int warp = tid >> 5, lane = tid & 31;
    const int n = blockIdx.x * 4 + warp;        // 4 warps per block
    const float4* xr = (const float4*)(x + (size_t)n * DIM);
    __half* hp = g_xh + (size_t)n * DIM;

    float p[NE];
#pragma unroll
    for (int e = 0; e < NE; e++) p[e] = 0.0f;

#pragma unroll
    for (int j = 0; j < 4; j++) {
        const int d4 = j * 32 + lane;           // float4 index in row (0..127)
        const int d0 = d4 * 4;
        float4 v = xr[d4];
        ((half2*)(hp + d0))[0] = __floats2half2_rn(v.x, v.y);
        ((half2*)(hp + d0))[1] = __floats2half2_rn(v.z, v.w);
#pragma unroll
        for (int e = 0; e < NE; e++) {
            const float4 w = *(const float4*)&wgt[e][d0];
            p[e] = fmaf(v.x, w.x, p[e]);
            p[e] = fmaf(v.y, w.y, p[e]);
            p[e] = fmaf(v.z, w.z, p[e]);
            p[e] = fmaf(v.w, w.w, p[e]);
        }
    }
#pragma unroll
    for (int o = 16; o; o >>= 1)
#pragma unroll
        for (int e = 0; e < NE; e++) p[e] += __shfl_xor_sync(0xffffffffu, p[e], o);

    if (lane == 0) {
#pragma unroll
        for (int e = 0; e < NE; e++) p[e] += bg[e];
        int i0 = 0;
#pragma unroll
        for (int e = 1; e < NE; e++) if (p[e] > p[i0]) i0 = e;
        int i1 = (i0 == 0) ? 1 : 0;
#pragma unroll
        for (int e = 0; e < NE; e++) if (e != i0 && p[e] > p[i1]) i1 = e;
        float w0 = 1.0f / (1.0f + expf(p[i1] - p[i0]));
        float w1 = 1.0f - w0;
        g_pw[2 * n + 0] = w0;
        g_pw[2 * n + 1] = w1;
        atomicAdd(&usage[i0], w0);
        atomicAdd(&usage[i1], w1);
        int q0 = atomicAdd(&g_cnt[i0], 1); g_list[i0 * NPAIR + q0] = 2 * n;
        int q1 = atomicAdd(&g_cnt[i1], 1); g_list[i1 * NPAIR + q1] = 2 * n + 1;
    }
}

// ---------------- grouped GEMM via wmma fp16 + 3-stage cp.async pipeline ----
// D[m,n] = sum_k A[m,k] * B[k,n] + bias[n]   (single-pass fp16, fp32 accum)
// A: gathered rows via g_list (row = pid>>ROWSH), K-major [*, KTOT]
// B: [E][KTOT][NTOT] row-major.  HALF_OUT: emit fp16 (fc1) else fp32 (fc2).
template<int KTOT, int NTOT, int ROWSH, bool HALF_OUT>
__device__ __forceinline__ void gemm_body(
        const __half* Amat, const __half* Bmat,
        const float* __restrict__ bias,
        __half* Oh, float* Ofp) {
    constexpr int NCH = KTOT / BK;
    extern __shared__ __align__(16) char sm[];

    const int e   = blockIdx.z;
    const int cnt = g_cnt[e];
    const int m0  = blockIdx.y * M_T;
    if (m0 >= cnt) return;
    const int n0  = blockIdx.x * N_T;
    const int tid  = threadIdx.x;
    const int wid  = tid >> 5;
    const int lane = tid & 31;
    const int wm = wid & 1;        // 2 warps along M: 64 rows each
    const int wn = wid >> 1;       // 2 warps along N: 64 cols each

    const uint32_t sb = smem_u32(sm);

    // ---- loader setup: 128 threads, 4 segs each for A and for B ------------
    uint32_t dA[4], aoff[4];       // aoff includes the column-16 byte offset
    uint32_t dB[4], boff[4];
#pragma unroll
    for (int j = 0; j < 4; j++) {
        const int s  = tid + 128 * j;
        const int ar = s >> 2, ac = (s & 3) * 16;       // A: 128 rows x 4 segs
        int am = m0 + ar; if (am >= cnt) am = m0;       // duplicate; discarded
        aoff[j] = (uint32_t)((g_list[e * NPAIR + am] >> ROWSH) * (KTOT * 2)) + ac;
        dA[j]   = (uint32_t)(ar * (ALD * 2) + ac);
        const int bk = s >> 4, bc = (s & 15) * 16;      // B: 32 rows x 16 segs
        dB[j]   = (uint32_t)(bk * (BLD * 2) + bc);
        boff[j] = (uint32_t)(((e * KTOT + bk) * NTOT + n0) * 2 + bc);
    }
    const char* pA = (const char*)Amat;
    const char* pB = (const char*)Bmat;

    auto issue = [&](int c) {
        const uint32_t st = sb + (uint32_t)(c % NSTG) * STG;
        const uint32_t ga = (uint32_t)c * (BK * 2);        // A: +64B per chunk
        const uint32_t gb = (uint32_t)c * (BK * NTOT * 2); // B: +32 k-rows
#pragma unroll
        for (int j = 0; j < 4; j++) {
            cpa16(st + SA + dA[j], pA + aoff[j] + ga);
            cpa16(st + SB + dB[j], pB + boff[j] + gb);
        }
        cpa_commit();
    };

    wmma::fragment<wmma::accumulator, 16, 16, 16, float> acc[4][4];
#pragma unroll
    for (int mi = 0; mi < 4; mi++)
#pragma unroll
        for (int nj = 0; nj < 4; nj++) wmma::fill_fragment(acc[mi][nj], 0.0f);

    issue(0);
    issue(1);                                  // NCH >= 16 always
    for (int c = 0; c < NCH; c++) {
        if (c + 1 < NCH) cpa_wait<1>();        // stage c arrived
        else             cpa_wait<0>();
        __syncthreads();                       // ...and visible to all warps

        const char* stg = sm + (size_t)(c % NSTG) * STG;
        const __half* sA = (const __half*)(stg + SA);
        const __half* sBp = (const __half*)(stg + SB);
#pragma unroll
        for (int ks = 0; ks < 2; ks++) {
            wmma::fragment<wmma::matrix_a, 16, 16, 16, __half,
                           wmma::row_major> af[4];
#pragma unroll
            for (int mi = 0; mi < 4; mi++) {
                const int ro = (wm * 64 + mi * 16) * ALD + ks * 16;
                wmma::load_matrix_sync(af[mi], sA + ro, ALD);
            }
#pragma unroll
            for (int nj = 0; nj < 4; nj++) {
                wmma::fragment<wmma::matrix_b, 16, 16, 16, __half,
                               wmma::row_major> bf;
                const int bo2 = (ks * 16) * BLD + wn * 64 + nj * 16;
                wmma::load_matrix_sync(bf, sBp + bo2, BLD);
#pragma unroll
                for (int mi = 0; mi < 4; mi++)
                    wmma::mma_sync(acc[mi][nj], af[mi], bf, acc[mi][nj]);
            }
        }
        if (c + 2 < NCH) issue(c + 2);         // into stage (c-1)%3: safe
    }
    __syncthreads();                            // done with tiles; reuse as cs

    // ---- epilogue: per-warp 16x16 fp32 staging (pitch 20) ------------------
    float* cs = reinterpret_cast<float*>(sm + wid * (16 * 20 * 4));
    const int r  = lane >> 1;
    const int c0 = (lane & 1) * 8;
#pragma unroll
    for (int mi = 0; mi < 4; mi++) {
#pragma unroll
        for (int nj = 0; nj < 4; nj++) {
            wmma::store_matrix_sync(cs, acc[mi][nj], 20, wmma::mem_row_major);
            __syncwarp();
            const int m = m0 + wm * 64 + mi * 16 + r;
            if (m < cnt) {
                const int pid = g_list[e * NPAIR + m];
                const int nc  = n0 + wn * 64 + nj * 16 + c0;
                const float* bp = bias + (size_t)e * NTOT + nc;
                const float* cp = cs + r * 20 + c0;
                if (HALF_OUT) {
                    __half* op = Oh + (size_t)pid * NTOT + nc;
#pragma unroll
                    for (int p = 0; p < 4; p++) {
                        float v0 = cp[2 * p + 0] + bp[2 * p + 0];
                        float v1 = cp[2 * p + 1] + bp[2 * p + 1];
                        *(half2*)(op + 2 * p) = __floats2half2_rn(v0, v1);
                    }
                } else {
                    float* op = Ofp + (size_t)pid * NTOT + nc;
                    float4 w0, w1;
                    w0.x = cp[0] + bp[0]; w0.y = cp[1] + bp[1];
                    w0.z = cp[2] + bp[2]; w0.w = cp[3] + bp[3];
                    w1.x = cp[4] + bp[4]; w1.y = cp[5] + bp[5];
                    w1.z = cp[6] + bp[6]; w1.w = cp[7] + bp[7];
                    *(float4*)(op + 0) = w0;
                    *(float4*)(op + 4) = w1;
                }
            }
            __syncwarp();                       // before cs is overwritten
        }
    }
}

// Concrete wrappers: globals referenced from DEVICE code (correct addresses).
__global__ void __launch_bounds__(128, 2) k_fc1g(const float* __restrict__ b1) {
    gemm_body<DIM, HID, 1, true>(g_xh, g_w1h, b1, g_Hh, nullptr);
}
__global__ void __launch_bounds__(128, 2) k_fc2g(const float* __restrict__ b2) {
    gemm_body<HID, DIM, 0, false>(g_Hh, g_w2h, b2, nullptr, g_O);
}

// ---------------- combine ----------------------------------------------------
__global__ void k_comb(float* __restrict__ out) {
    int idx = blockIdx.x * blockDim.x + threadIdx.x;
    if (idx >= N_TOK * DIM / 4) return;
    int n  = idx / (DIM / 4);
    int d4 = idx % (DIM / 4);
    float w0 = g_pw[2 * n + 0];
    float w1 = g_pw[2 * n + 1];
    float4 a = *(const float4*)(g_O + (size_t)(2 * n + 0) * DIM + d4 * 4);
    float4 b = *(const float4*)(g_O + (size_t)(2 * n + 1) * DIM + d4 * 4);
    float4 r;
    r.x = w0 * a.x + w1 * b.x;
    r.y = w0 * a.y + w1 * b.y;
    r.z = w0 * a.z + w1 * b.z;
    r.w = w0 * a.w + w1 * b.w;
    *(float4*)(out + (size_t)idx * 4) = r;
}

// ---------------------------------------------------------------------------
extern "C" void kernel_launch(void* const* d_in, const int* in_sizes, int n_in,
                              void* d_out, int out_size) {
    const float* x  = (const float*)d_in[0];
    const float* Wg = (const float*)d_in[1];
    const float* bg = (const float*)d_in[2];
    const float* W1 = (const float*)d_in[3];
    const float* b1 = (const float*)d_in[4];
    const float* W2 = (const float*)d_in[5];
    const float* b2 = (const float*)d_in[6];
    float* out   = (float*)d_out;
    float* usage = out + (size_t)N_TOK * DIM;

    cudaFuncSetAttribute(k_fc1g, cudaFuncAttributeMaxDynamicSharedMemorySize,
                         SMEM_DYN);
    cudaFuncSetAttribute(k_fc2g, cudaFuncAttributeMaxDynamicSharedMemorySize,
                         SMEM_DYN);

    k_zero<<<1, 32>>>(usage);
    k_split_w<<<(2 * NE * DIM * HID / 4 + 255) / 256, 256>>>(W1, W2);
    k_gatesplit<<<N_TOK / 4, 128>>>(x, Wg, bg, usage);
    k_fc1g<<<dim3(HID / N_T, NPAIR / M_T, NE), 128, SMEM_DYN>>>(b1);
    k_fc2g<<<dim3(DIM / N_T, NPAIR / M_T, NE), 128, SMEM_DYN>>>(b2);
    k_comb<<<(N_TOK * DIM / 4) / 256, 256>>>(out);
}